// round 9
// baseline (speedup 1.0000x reference)
#include <cuda_runtime.h>
#include <cuda_bf16.h>
#include <math.h>
#include <stdint.h>

// Problem constants
#define BATCH 4
#define HH 56
#define WW 56
#define CC 256
#define NHEAD 8
#define HD 32
#define KS 7
#define PADR 3
#define M_TOTAL (BATCH * HH * WW)   // 12544
#define QKV_N (3 * CC)              // 768
#define GK 256                      // K of both GEMMs

// Scratch (device globals: allocation-free rule)
__device__ float g_qkv[M_TOTAL * QKV_N];    // [pix][768] q|k|v, q pre-scaled
__device__ float g_attnT[CC * M_TOTAL];     // attention out, TRANSPOSED [C][M], tf32
__device__ float g_xt[CC * M_TOTAL];        // x transposed [C][M], tf32
__device__ float g_wq[CC * QKV_N];          // w_qkv [K][N], tf32
__device__ float g_wp[CC * CC];             // w_proj [K][N], tf32

__device__ __forceinline__ unsigned f2tf32(float x) {
    unsigned r;
    asm("cvt.rna.tf32.f32 %0, %1;" : "=r"(r) : "f"(x));
    return r;
}
__device__ __forceinline__ uint32_t smem_u32(const void* p) {
    uint32_t a;
    asm("{ .reg .u64 t; cvta.to.shared.u64 t, %1; cvt.u32.u64 %0, t; }"
        : "=r"(a) : "l"(p));
    return a;
}
__device__ __forceinline__ void cp16(uint32_t dst, const void* src) {
    asm volatile("cp.async.cg.shared.global [%0], [%1], 16;\n"
                 :: "r"(dst), "l"(src));
}
#define CP_COMMIT() asm volatile("cp.async.commit_group;\n" ::: "memory")
#define CP_WAIT2()  asm volatile("cp.async.wait_group 2;\n" ::: "memory")

// ---------------------------------------------------------------------------
// Prep kernels
// ---------------------------------------------------------------------------
__global__ void tf32_round_kernel(const float4* __restrict__ in,
                                  float4* __restrict__ out, int n4)
{
    const int i = blockIdx.x * 256 + threadIdx.x;
    if (i < n4) {
        float4 v = in[i];
        v.x = __uint_as_float(f2tf32(v.x));
        v.y = __uint_as_float(f2tf32(v.y));
        v.z = __uint_as_float(f2tf32(v.z));
        v.w = __uint_as_float(f2tf32(v.w));
        out[i] = v;
    }
}

// x [M][C] -> xt [C][M], tf32-rounded
__global__ void transpose_round_x(const float* __restrict__ in,
                                  float* __restrict__ out)
{
    __shared__ float tile[32][33];
    const int m0 = blockIdx.x * 32;
    const int k0 = blockIdx.y * 32;
    for (int i = threadIdx.y; i < 32; i += 8)
        tile[i][threadIdx.x] = in[(size_t)(m0 + i) * CC + k0 + threadIdx.x];
    __syncthreads();
    for (int i = threadIdx.y; i < 32; i += 8)
        out[(size_t)(k0 + i) * M_TOTAL + m0 + threadIdx.x] =
            __uint_as_float(f2tf32(tile[threadIdx.x][i]));
}

// ---------------------------------------------------------------------------
// cp.async 4-stage TF32 GEMM (unchanged from round 8).
// ---------------------------------------------------------------------------
#define NSTAGE 4
#define A_PITCH 136
#define B_PITCH 72
#define ASTG_B (32 * A_PITCH * 4)      // 17408
#define BSTG_B (32 * B_PITCH * 4)      // 9216
#define STG_B  (ASTG_B + BSTG_B)       // 26624
#define GEMM_SMEM (NSTAGE * STG_B)     // 106496

__device__ __forceinline__ void mma_tf32(float4& d,
    float a0, float a1, float a2, float a3, float b0, float b1)
{
    asm volatile(
        "mma.sync.aligned.m16n8k8.row.col.f32.tf32.tf32.f32 "
        "{%0,%1,%2,%3},{%4,%5,%6,%7},{%8,%9},{%0,%1,%2,%3};\n"
        : "+f"(d.x), "+f"(d.y), "+f"(d.z), "+f"(d.w)
        : "r"(__float_as_uint(a0)), "r"(__float_as_uint(a1)),
          "r"(__float_as_uint(a2)), "r"(__float_as_uint(a3)),
          "r"(__float_as_uint(b0)), "r"(__float_as_uint(b1)));
}

__global__ __launch_bounds__(256, 2) void tgemm_ca(
    const float* __restrict__ At, const float* __restrict__ B,
    const float* __restrict__ bias, float* __restrict__ C,
    int M, int N, int scaleCols, float scale)
{
    extern __shared__ float sm[];
    const uint32_t sb = smem_u32(sm);
    const int tid  = threadIdx.x;
    const int wid  = tid >> 5;
    const int lane = tid & 31;
    const int warp_m = wid & 3;
    const int warp_n = wid >> 2;
    const int t  = lane & 3;           // k within quad
    const int qr = lane >> 2;          // group row 0..7
    const int bm = blockIdx.y << 7;
    const int bn = blockIdx.x << 6;

    const int lr = tid >> 3;
    const int lc = tid & 7;
    const float* Asrc = At + (size_t)lr * M + bm + lc * 4;
    const float* Bsrc = B + (size_t)lr * N + bn + lc * 4;
    const uint32_t aOff = (uint32_t)(lr * A_PITCH + lc * 4) * 4u;
    const uint32_t bOff = (uint32_t)ASTG_B + (uint32_t)(lr * B_PITCH + lc * 4) * 4u;

    float acc[2][4][4];
    #pragma unroll
    for (int mt = 0; mt < 2; ++mt)
        #pragma unroll
        for (int nt = 0; nt < 4; ++nt)
            #pragma unroll
            for (int i = 0; i < 4; ++i) acc[mt][nt][i] = 0.f;

    #pragma unroll
    for (int s = 0; s < NSTAGE - 1; ++s) {
        const uint32_t sd = sb + s * STG_B;
        #pragma unroll
        for (int e = 0; e < 4; ++e)
            cp16(sd + aOff + e * 128u, Asrc + (size_t)s * 32 * M + e * 32);
        #pragma unroll
        for (int e = 0; e < 2; ++e)
            cp16(sd + bOff + e * 128u, Bsrc + (size_t)s * 32 * N + e * 32);
        CP_COMMIT();
    }

    #pragma unroll 1
    for (int kt = 0; kt < 8; ++kt) {
        CP_WAIT2();
        __syncthreads();

        if (kt + 3 < 8) {
            const uint32_t sd = sb + ((kt + 3) & 3) * STG_B;
            #pragma unroll
            for (int e = 0; e < 4; ++e)
                cp16(sd + aOff + e * 128u, Asrc + (size_t)(kt + 3) * 32 * M + e * 32);
            #pragma unroll
            for (int e = 0; e < 2; ++e)
                cp16(sd + bOff + e * 128u, Bsrc + (size_t)(kt + 3) * 32 * N + e * 32);
        }
        CP_COMMIT();

        const float* as = sm + (kt & 3) * (STG_B / 4) + warp_m * 32 + qr;
        const float* bs = sm + (kt & 3) * (STG_B / 4) + (ASTG_B / 4) + warp_n * 32 + qr;
        #pragma unroll
        for (int ss = 0; ss < 4; ++ss) {
            const float* ap = as + (ss * 8 + t) * A_PITCH;
            const float* bp = bs + (ss * 8 + t) * B_PITCH;
            float a0[2], a1[2], a2[2], a3[2];
            #pragma unroll
            for (int mt = 0; mt < 2; ++mt) {
                a0[mt] = ap[mt * 16];
                a1[mt] = ap[mt * 16 + 8];
                a2[mt] = ap[mt * 16 + 4 * A_PITCH];
                a3[mt] = ap[mt * 16 + 8 + 4 * A_PITCH];
            }
            float b0[4], b1[4];
            #pragma unroll
            for (int nt = 0; nt < 4; ++nt) {
                b0[nt] = bp[nt * 8];
                b1[nt] = bp[nt * 8 + 4 * B_PITCH];
            }
            #pragma unroll
            for (int mt = 0; mt < 2; ++mt)
                #pragma unroll
                for (int nt = 0; nt < 4; ++nt)
                    mma_tf32(*(float4*)acc[mt][nt],
                             a0[mt], a1[mt], a2[mt], a3[mt],
                             b0[nt], b1[nt]);
        }
    }

    const float sc = (bn < scaleCols) ? scale : 1.f;
    #pragma unroll
    for (int nt = 0; nt < 4; ++nt) {
        const int gn = bn + warp_n * 32 + nt * 8 + 2 * t;
        const float2 bz = *(const float2*)&bias[gn];
        #pragma unroll
        for (int mt = 0; mt < 2; ++mt) {
            const int gm = bm + warp_m * 32 + mt * 16 + qr;
            float2 r0, r1;
            r0.x = (acc[mt][nt][0] + bz.x) * sc;
            r0.y = (acc[mt][nt][1] + bz.y) * sc;
            r1.x = (acc[mt][nt][2] + bz.x) * sc;
            r1.y = (acc[mt][nt][3] + bz.y) * sc;
            *(float2*)&C[(size_t)gm * N + gn] = r0;
            *(float2*)&C[(size_t)(gm + 8) * N + gn] = r1;
        }
    }
}

// ---------------------------------------------------------------------------
// Neighborhood attention. One block = (batch, head, 8x8 query tile).
// Register softmax + quad-shfl weight broadcast. AV dim-split: thread g owns
// 16B chunks {g, g+4} (dims 4g..4g+3, 16+4g..19+4g) -> lane chunk index
// 9*row + g (+4): conflict-free (9*dqx = -dg mod 32 unsolvable for |dg|<=3).
// Output written TRANSPOSED ([C][M], tf32-rounded) for the proj GEMM.
// ---------------------------------------------------------------------------
#define TQ 8
#define WIN 14
#define KP 36
#define ATTN_SMEM_FLOATS (2 * WIN * WIN * KP + 52)
#define ATTN_SMEM_BYTES (ATTN_SMEM_FLOATS * 4)

__global__ __launch_bounds__(256) void na2d_attn(
    const float* __restrict__ qkv, const float* __restrict__ rpb,
    float* __restrict__ outT)
{
    extern __shared__ float sm[];
    float* ks_  = sm;
    float* vs_  = sm + WIN * WIN * KP;
    float* rpbs = sm + 2 * WIN * WIN * KP;

    const int b    = blockIdx.z;
    const int head = blockIdx.y;
    const int tY   = blockIdx.x / 7;
    const int tX   = blockIdx.x - tY * 7;
    const int oy   = tY * TQ;
    const int ox   = tX * TQ;
    const int tid  = threadIdx.x;

    if (tid < 49) rpbs[tid] = rpb[head * 49 + tid];
    const bool interior = (tY >= 1) && (tY <= 5) && (tX >= 1) && (tX <= 5);
    if (interior) {
        #pragma unroll 1
        for (int idx = tid; idx < WIN * WIN * 8; idx += 256) {
            const int row = idx >> 3;
            const int d4  = idx & 7;
            const int wy = row / WIN, wx = row - wy * WIN;
            const int gy = oy - PADR + wy, gx = ox - PADR + wx;
            const float* p = qkv + (size_t)(((b * HH + gy) * WW) + gx) * QKV_N
                           + head * HD + d4 * 4;
            *(float4*)&ks_[row * KP + d4 * 4] = *(const float4*)(p + 256);
            *(float4*)&vs_[row * KP + d4 * 4] = *(const float4*)(p + 512);
        }
    } else {
        #pragma unroll 1
        for (int idx = tid; idx < WIN * WIN * 8; idx += 256) {
            const int row = idx >> 3;
            const int d4  = idx & 7;
            const int wy = row / WIN, wx = row - wy * WIN;
            const int gy = oy - PADR + wy, gx = ox - PADR + wx;
            float4 kv = make_float4(0.f, 0.f, 0.f, 0.f);
            float4 vv = make_float4(0.f, 0.f, 0.f, 0.f);
            if (gy >= 0 && gy < HH && gx >= 0 && gx < WW) {
                const float* p = qkv + (size_t)(((b * HH + gy) * WW) + gx) * QKV_N
                               + head * HD + d4 * 4;
                kv = *(const float4*)(p + 256);
                vv = *(const float4*)(p + 512);
            }
            *(float4*)&ks_[row * KP + d4 * 4] = kv;
            *(float4*)&vs_[row * KP + d4 * 4] = vv;
        }
    }

    const int qi = tid >> 2;
    const int g  = tid & 3;
    const int qy = qi >> 3, qx = qi & 7;
    const size_t qpix = (size_t)((b * HH + oy + qy) * WW) + ox + qx;
    const float4* qp = (const float4*)(qkv + qpix * QKV_N + head * HD);
    float4 qv[8];
    #pragma unroll
    for (int cc = 0; cc < 8; ++cc) qv[cc] = qp[cc];

    __syncthreads();

    float sv[13];
    #pragma unroll
    for (int u = 0; u < 13; ++u) {
        const int j = g + 4 * u;
        const bool act = (j < 49);
        const int jc = act ? j : 48;
        const int di = jc / 7, dj = jc - di * 7;
        const float4* kr = (const float4*)(ks_ + ((qy + di) * WIN + qx + dj) * KP);
        float s0 = 0.f, s1 = 0.f, s2 = 0.f, s3 = 0.f;
        #pragma unroll
        for (int cc = 0; cc < 8; cc += 2) {
            const float4 k0 = kr[cc], k1 = kr[cc + 1];
            s0 = fmaf(qv[cc].x, k0.x, s0);
            s1 = fmaf(qv[cc].y, k0.y, s1);
            s2 = fmaf(qv[cc].z, k0.z, s2);
            s3 = fmaf(qv[cc].w, k0.w, s3);
            s0 = fmaf(qv[cc+1].x, k1.x, s0);
            s1 = fmaf(qv[cc+1].y, k1.y, s1);
            s2 = fmaf(qv[cc+1].z, k1.z, s2);
            s3 = fmaf(qv[cc+1].w, k1.w, s3);
        }
        sv[u] = act ? ((s0 + s1) + (s2 + s3) + rpbs[jc]) : -1e30f;
    }

    float m = sv[0];
    #pragma unroll
    for (int u = 1; u < 13; ++u) m = fmaxf(m, sv[u]);
    m = fmaxf(m, __shfl_xor_sync(0xffffffffu, m, 1));
    m = fmaxf(m, __shfl_xor_sync(0xffffffffu, m, 2));
    float ssum = 0.f;
    #pragma unroll
    for (int u = 0; u < 13; ++u) {
        const float e = __expf(sv[u] - m);
        sv[u] = e;
        ssum += e;
    }
    ssum += __shfl_xor_sync(0xffffffffu, ssum, 1);
    ssum += __shfl_xor_sync(0xffffffffu, ssum, 2);
    const float inv = 1.f / ssum;
    #pragma unroll
    for (int u = 0; u < 13; ++u) sv[u] *= inv;

    // --- AV: thread g owns dims [4g,4g+4) and [16+4g,16+4g+4) ---
    const int lanebase = (tid & 31) & ~3;
    float4 a0 = make_float4(0.f, 0.f, 0.f, 0.f);
    float4 a1 = make_float4(0.f, 0.f, 0.f, 0.f);
    #pragma unroll
    for (int di = 0; di < 7; ++di) {
        const float* vrow = vs_ + ((qy + di) * WIN + qx) * KP + g * 4;
        #pragma unroll
        for (int dj = 0; dj < 7; ++dj) {
            const int j = di * 7 + dj;
            const float w = __shfl_sync(0xffffffffu, sv[j >> 2],
                                        lanebase | (j & 3));
            const float4 v0 = *(const float4*)(vrow + dj * KP);        // chunk g
            const float4 v1 = *(const float4*)(vrow + dj * KP + 16);   // chunk g+4
            a0.x = fmaf(w, v0.x, a0.x); a0.y = fmaf(w, v0.y, a0.y);
            a0.z = fmaf(w, v0.z, a0.z); a0.w = fmaf(w, v0.w, a0.w);
            a1.x = fmaf(w, v1.x, a1.x); a1.y = fmaf(w, v1.y, a1.y);
            a1.z = fmaf(w, v1.z, a1.z); a1.w = fmaf(w, v1.w, a1.w);
        }
    }
    // transposed, tf32-rounded output: rows head*32 + {4g..4g+3, 16+4g..19+4g}
    float* op = outT + (size_t)(head * HD + 4 * g) * M_TOTAL + qpix;
    op[0 * M_TOTAL] = __uint_as_float(f2tf32(a0.x));
    op[1 * M_TOTAL] = __uint_as_float(f2tf32(a0.y));
    op[2 * M_TOTAL] = __uint_as_float(f2tf32(a0.z));
    op[3 * M_TOTAL] = __uint_as_float(f2tf32(a0.w));
    float* op2 = outT + (size_t)(head * HD + 16 + 4 * g) * M_TOTAL + qpix;
    op2[0 * M_TOTAL] = __uint_as_float(f2tf32(a1.x));
    op2[1 * M_TOTAL] = __uint_as_float(f2tf32(a1.y));
    op2[2 * M_TOTAL] = __uint_as_float(f2tf32(a1.z));
    op2[3 * M_TOTAL] = __uint_as_float(f2tf32(a1.w));
}

// ---------------------------------------------------------------------------
extern "C" void kernel_launch(void* const* d_in, const int* in_sizes, int n_in,
                              void* d_out, int out_size)
{
    (void)in_sizes; (void)n_in; (void)out_size;
    const float* x      = (const float*)d_in[0];
    const float* w_qkv  = (const float*)d_in[1];
    const float* b_qkv  = (const float*)d_in[2];
    const float* rpb    = (const float*)d_in[3];
    const float* w_proj = (const float*)d_in[4];
    const float* b_proj = (const float*)d_in[5];
    float* out = (float*)d_out;

    float *qkvb = nullptr, *attnT = nullptr, *xt = nullptr, *wq = nullptr, *wp = nullptr;
    cudaGetSymbolAddress((void**)&qkvb, g_qkv);
    cudaGetSymbolAddress((void**)&attnT, g_attnT);
    cudaGetSymbolAddress((void**)&xt, g_xt);
    cudaGetSymbolAddress((void**)&wq, g_wq);
    cudaGetSymbolAddress((void**)&wp, g_wp);

    cudaFuncSetAttribute(tgemm_ca, cudaFuncAttributeMaxDynamicSharedMemorySize,
                         GEMM_SMEM);
    cudaFuncSetAttribute(na2d_attn, cudaFuncAttributeMaxDynamicSharedMemorySize,
                         ATTN_SMEM_BYTES);

    const float qscale = 0.17677669529663689f; // 32^-0.5

    // 0) prep: transpose+round x -> [C][M]; round weights ([K][N] kept)
    transpose_round_x<<<dim3(M_TOTAL / 32, CC / 32), dim3(32, 8)>>>(x, xt);
    {
        const int nq = CC * QKV_N / 4;
        tf32_round_kernel<<<(nq + 255) / 256, 256>>>((const float4*)w_qkv, (float4*)wq, nq);
        const int np = CC * CC / 4;
        tf32_round_kernel<<<(np + 255) / 256, 256>>>((const float4*)w_proj, (float4*)wp, np);
    }

    // 1) qkv = x @ w_qkv + b_qkv  (q columns pre-scaled)
    tgemm_ca<<<dim3(QKV_N / 64, M_TOTAL / 128), 256, GEMM_SMEM>>>(
        xt, wq, b_qkv, qkvb, M_TOTAL, QKV_N, 256, qscale);

    // 2) neighborhood attention (writes transposed tf32 output)
    na2d_attn<<<dim3(49, NHEAD, BATCH), 256, ATTN_SMEM_BYTES>>>(qkvb, rpb, attnT);

    // 3) out = attn @ w_proj + b_proj
    tgemm_ca<<<dim3(CC / 64, M_TOTAL / 128), 256, GEMM_SMEM>>>(
        attnT, wp, b_proj, out, M_TOTAL, CC, 0, 1.f);
}

// round 10
// speedup vs baseline: 1.1992x; 1.1992x over previous
#include <cuda_runtime.h>
#include <cuda_bf16.h>
#include <math.h>
#include <stdint.h>

// Problem constants
#define BATCH 4
#define HH 56
#define WW 56
#define CC 256
#define NHEAD 8
#define HD 32
#define KS 7
#define PADR 3
#define M_TOTAL (BATCH * HH * WW)   // 12544
#define QKV_N (3 * CC)              // 768
#define GK 256                      // K of both GEMMs

// Scratch (device globals: allocation-free rule)
__device__ float g_qkv[M_TOTAL * QKV_N];   // [pix][768] q|k|v, q pre-scaled
__device__ float g_attn[M_TOTAL * CC];     // attention out [M][C], tf32-rounded

__device__ __forceinline__ unsigned f2tf32(float x) {
    unsigned r;
    asm("cvt.rna.tf32.f32 %0, %1;" : "=r"(r) : "f"(x));
    return r;
}
__device__ __forceinline__ float tfr(float x) {
    return __uint_as_float(f2tf32(x));
}
__device__ __forceinline__ uint32_t smem_u32(const void* p) {
    uint32_t a;
    asm("{ .reg .u64 t; cvta.to.shared.u64 t, %1; cvt.u32.u64 %0, t; }"
        : "=r"(a) : "l"(p));
    return a;
}
__device__ __forceinline__ void cp16(uint32_t dst, const void* src) {
    asm volatile("cp.async.cg.shared.global [%0], [%1], 16;\n"
                 :: "r"(dst), "l"(src));
}
#define CP_COMMIT() asm volatile("cp.async.commit_group;\n" ::: "memory")
#define CP_WAIT2()  asm volatile("cp.async.wait_group 2;\n" ::: "memory")

// ---------------------------------------------------------------------------
// cp.async 4-stage TF32 GEMM, raw fp32 inputs (RNA->tf32 applied in-register
// on fragments; numerically identical to pre-rounding the operands).
// A [M][K=256] row-major, B [K=256][N] row-major. C[M][N] = A @ B + bias.
// Block tile 128x64x32, 256 thr = 8 warps (4Mx2N), warp tile 32x32,
// mma.m16n8k8. A smem [m][k] pitch 36 -> lane bank = 4*qr+t (conflict-free);
// B smem [k][n] pitch 72 -> lane bank = 8*t+qr (conflict-free).
// 4 stages = 108KB, 2 blocks/SM, 3-tile cp.async lookahead (hides DRAM).
// ---------------------------------------------------------------------------
#define NSTAGE 4
#define A_PITCH 36                     // floats per A row (32 + 4 pad)
#define B_PITCH 72                     // floats per B row (64 + 8 pad)
#define ASTG_B (128 * A_PITCH * 4)     // 18432
#define BSTG_B (32 * B_PITCH * 4)      // 9216
#define STG_B  (ASTG_B + BSTG_B)       // 27648
#define GEMM_SMEM (NSTAGE * STG_B)     // 110592

__device__ __forceinline__ void mma_tf32(float4& d,
    unsigned a0, unsigned a1, unsigned a2, unsigned a3,
    unsigned b0, unsigned b1)
{
    asm volatile(
        "mma.sync.aligned.m16n8k8.row.col.f32.tf32.tf32.f32 "
        "{%0,%1,%2,%3},{%4,%5,%6,%7},{%8,%9},{%0,%1,%2,%3};\n"
        : "+f"(d.x), "+f"(d.y), "+f"(d.z), "+f"(d.w)
        : "r"(a0), "r"(a1), "r"(a2), "r"(a3), "r"(b0), "r"(b1));
}

__global__ __launch_bounds__(256, 2) void tgemm_ca(
    const float* __restrict__ A, const float* __restrict__ B,
    const float* __restrict__ bias, float* __restrict__ C,
    int N, int scaleCols, float scale)
{
    extern __shared__ float sm[];
    const uint32_t sb = smem_u32(sm);
    const int tid  = threadIdx.x;
    const int wid  = tid >> 5;
    const int lane = tid & 31;
    const int warp_m = wid & 3;
    const int warp_n = wid >> 2;
    const int t  = lane & 3;           // k within quad
    const int qr = lane >> 2;          // group row 0..7
    const int bm = blockIdx.y << 7;
    const int bn = blockIdx.x << 6;

    // A load mapping: base row lr = tid>>3 (0..31), rows lr+32e (e=0..3),
    // 16B chunk lc within the 128B row.
    const int lr = tid >> 3;
    const int lc = tid & 7;
    const float* Asrc = A + (size_t)(bm + lr) * GK + lc * 4;
    const uint32_t aOff = (uint32_t)(lr * A_PITCH + lc * 4) * 4u;
    // B load mapping: k-row lr (0..31), col chunk lc*4 + 32e (e=0..1)
    const float* Bsrc = B + (size_t)lr * N + bn + lc * 4;
    const uint32_t bOff = (uint32_t)ASTG_B + (uint32_t)(lr * B_PITCH + lc * 4) * 4u;

    float acc[2][4][4];
    #pragma unroll
    for (int mt = 0; mt < 2; ++mt)
        #pragma unroll
        for (int nt = 0; nt < 4; ++nt)
            #pragma unroll
            for (int i = 0; i < 4; ++i) acc[mt][nt][i] = 0.f;

    // prologue: stages 0..2 <- k-tiles 0..2
    #pragma unroll
    for (int s = 0; s < NSTAGE - 1; ++s) {
        const uint32_t sd = sb + s * STG_B;
        #pragma unroll
        for (int e = 0; e < 4; ++e)
            cp16(sd + aOff + e * (32u * A_PITCH * 4u),
                 Asrc + (size_t)e * 32 * GK + s * 32);
        #pragma unroll
        for (int e = 0; e < 2; ++e)
            cp16(sd + bOff + e * 128u, Bsrc + (size_t)s * 32 * N + e * 32);
        CP_COMMIT();
    }

    #pragma unroll 1
    for (int kt = 0; kt < 8; ++kt) {
        CP_WAIT2();          // tile kt resident
        __syncthreads();

        if (kt + 3 < 8) {
            const uint32_t sd = sb + ((kt + 3) & 3) * STG_B;
            #pragma unroll
            for (int e = 0; e < 4; ++e)
                cp16(sd + aOff + e * (32u * A_PITCH * 4u),
                     Asrc + (size_t)e * 32 * GK + (kt + 3) * 32);
            #pragma unroll
            for (int e = 0; e < 2; ++e)
                cp16(sd + bOff + e * 128u, Bsrc + (size_t)(kt + 3) * 32 * N + e * 32);
        }
        CP_COMMIT();         // always commit (keeps wait_group arithmetic exact)

        const float* as = sm + (kt & 3) * (STG_B / 4) + (warp_m * 32) * A_PITCH;
        const float* bs = sm + (kt & 3) * (STG_B / 4) + (ASTG_B / 4)
                          + warp_n * 32 + qr;
        #pragma unroll
        for (int ss = 0; ss < 4; ++ss) {
            const int kk = ss * 8 + t;
            const float* ap = as + kk;
            const float* bp = bs + kk * B_PITCH;
            unsigned a0[2], a1[2], a2[2], a3[2];
            #pragma unroll
            for (int mt = 0; mt < 2; ++mt) {
                a0[mt] = f2tf32(ap[(mt * 16 + qr) * A_PITCH]);
                a1[mt] = f2tf32(ap[(mt * 16 + qr + 8) * A_PITCH]);
                a2[mt] = f2tf32(ap[(mt * 16 + qr) * A_PITCH + 4]);
                a3[mt] = f2tf32(ap[(mt * 16 + qr + 8) * A_PITCH + 4]);
            }
            unsigned b0[4], b1[4];
            #pragma unroll
            for (int nt = 0; nt < 4; ++nt) {
                b0[nt] = f2tf32(bp[nt * 8]);
                b1[nt] = f2tf32(bp[nt * 8 + 4 * B_PITCH]);
            }
            #pragma unroll
            for (int mt = 0; mt < 2; ++mt)
                #pragma unroll
                for (int nt = 0; nt < 4; ++nt)
                    mma_tf32(*(float4*)acc[mt][nt],
                             a0[mt], a1[mt], a2[mt], a3[mt],
                             b0[nt], b1[nt]);
        }
    }

    const float sc = (bn < scaleCols) ? scale : 1.f;
    #pragma unroll
    for (int nt = 0; nt < 4; ++nt) {
        const int gn = bn + warp_n * 32 + nt * 8 + 2 * t;
        const float2 bz = *(const float2*)&bias[gn];
        #pragma unroll
        for (int mt = 0; mt < 2; ++mt) {
            const int gm = bm + warp_m * 32 + mt * 16 + qr;
            float2 r0, r1;
            r0.x = (acc[mt][nt][0] + bz.x) * sc;
            r0.y = (acc[mt][nt][1] + bz.y) * sc;
            r1.x = (acc[mt][nt][2] + bz.x) * sc;
            r1.y = (acc[mt][nt][3] + bz.y) * sc;
            *(float2*)&C[(size_t)gm * N + gn] = r0;
            *(float2*)&C[(size_t)(gm + 8) * N + gn] = r1;
        }
    }
}

// ---------------------------------------------------------------------------
// Neighborhood attention (proven round-6/8 body). One block = (batch, head,
// 8x8 query tile). Register softmax + quad-shfl weight broadcast.
// Output [M][C] natural layout, tf32-RNA-rounded for the proj GEMM.
// ---------------------------------------------------------------------------
#define TQ 8
#define WIN 14
#define KP 36
#define ATTN_SMEM_FLOATS (2 * WIN * WIN * KP + 52)
#define ATTN_SMEM_BYTES (ATTN_SMEM_FLOATS * 4)

__global__ __launch_bounds__(256) void na2d_attn(
    const float* __restrict__ qkv, const float* __restrict__ rpb,
    float* __restrict__ out)
{
    extern __shared__ float sm[];
    float* ks_  = sm;
    float* vs_  = sm + WIN * WIN * KP;
    float* rpbs = sm + 2 * WIN * WIN * KP;

    const int b    = blockIdx.z;
    const int head = blockIdx.y;
    const int tY   = blockIdx.x / 7;
    const int tX   = blockIdx.x - tY * 7;
    const int oy   = tY * TQ;
    const int ox   = tX * TQ;
    const int tid  = threadIdx.x;

    if (tid < 49) rpbs[tid] = rpb[head * 49 + tid];
    const bool interior = (tY >= 1) && (tY <= 5) && (tX >= 1) && (tX <= 5);
    if (interior) {
        #pragma unroll 1
        for (int idx = tid; idx < WIN * WIN * 8; idx += 256) {
            const int row = idx >> 3;
            const int d4  = idx & 7;
            const int wy = row / WIN, wx = row - wy * WIN;
            const int gy = oy - PADR + wy, gx = ox - PADR + wx;
            const float* p = qkv + (size_t)(((b * HH + gy) * WW) + gx) * QKV_N
                           + head * HD + d4 * 4;
            *(float4*)&ks_[row * KP + d4 * 4] = *(const float4*)(p + 256);
            *(float4*)&vs_[row * KP + d4 * 4] = *(const float4*)(p + 512);
        }
    } else {
        #pragma unroll 1
        for (int idx = tid; idx < WIN * WIN * 8; idx += 256) {
            const int row = idx >> 3;
            const int d4  = idx & 7;
            const int wy = row / WIN, wx = row - wy * WIN;
            const int gy = oy - PADR + wy, gx = ox - PADR + wx;
            float4 kv = make_float4(0.f, 0.f, 0.f, 0.f);
            float4 vv = make_float4(0.f, 0.f, 0.f, 0.f);
            if (gy >= 0 && gy < HH && gx >= 0 && gx < WW) {
                const float* p = qkv + (size_t)(((b * HH + gy) * WW) + gx) * QKV_N
                               + head * HD + d4 * 4;
                kv = *(const float4*)(p + 256);
                vv = *(const float4*)(p + 512);
            }
            *(float4*)&ks_[row * KP + d4 * 4] = kv;
            *(float4*)&vs_[row * KP + d4 * 4] = vv;
        }
    }

    const int qi = tid >> 2;
    const int g  = tid & 3;
    const int qy = qi >> 3, qx = qi & 7;
    const size_t qpix = (size_t)((b * HH + oy + qy) * WW) + ox + qx;
    const float4* qp = (const float4*)(qkv + qpix * QKV_N + head * HD);
    float4 qv[8];
    #pragma unroll
    for (int cc = 0; cc < 8; ++cc) qv[cc] = qp[cc];

    __syncthreads();

    float sv[13];
    #pragma unroll
    for (int u = 0; u < 13; ++u) {
        const int j = g + 4 * u;
        const bool act = (j < 49);
        const int jc = act ? j : 48;
        const int di = jc / 7, dj = jc - di * 7;
        const float4* kr = (const float4*)(ks_ + ((qy + di) * WIN + qx + dj) * KP);
        float s0 = 0.f, s1 = 0.f, s2 = 0.f, s3 = 0.f;
        #pragma unroll
        for (int cc = 0; cc < 8; cc += 2) {
            const float4 k0 = kr[cc], k1 = kr[cc + 1];
            s0 = fmaf(qv[cc].x, k0.x, s0);
            s1 = fmaf(qv[cc].y, k0.y, s1);
            s2 = fmaf(qv[cc].z, k0.z, s2);
            s3 = fmaf(qv[cc].w, k0.w, s3);
            s0 = fmaf(qv[cc+1].x, k1.x, s0);
            s1 = fmaf(qv[cc+1].y, k1.y, s1);
            s2 = fmaf(qv[cc+1].z, k1.z, s2);
            s3 = fmaf(qv[cc+1].w, k1.w, s3);
        }
        sv[u] = act ? ((s0 + s1) + (s2 + s3) + rpbs[jc]) : -1e30f;
    }

    float m = sv[0];
    #pragma unroll
    for (int u = 1; u < 13; ++u) m = fmaxf(m, sv[u]);
    m = fmaxf(m, __shfl_xor_sync(0xffffffffu, m, 1));
    m = fmaxf(m, __shfl_xor_sync(0xffffffffu, m, 2));
    float ssum = 0.f;
    #pragma unroll
    for (int u = 0; u < 13; ++u) {
        const float e = __expf(sv[u] - m);
        sv[u] = e;
        ssum += e;
    }
    ssum += __shfl_xor_sync(0xffffffffu, ssum, 1);
    ssum += __shfl_xor_sync(0xffffffffu, ssum, 2);
    const float inv = 1.f / ssum;
    #pragma unroll
    for (int u = 0; u < 13; ++u) sv[u] *= inv;

    const int lanebase = (tid & 31) & ~3;
    float4 a0 = make_float4(0.f, 0.f, 0.f, 0.f);
    float4 a1 = make_float4(0.f, 0.f, 0.f, 0.f);
    #pragma unroll
    for (int di = 0; di < 7; ++di) {
        const float* vrow = vs_ + ((qy + di) * WIN + qx) * KP + g * 8;
        #pragma unroll
        for (int dj = 0; dj < 7; ++dj) {
            const int j = di * 7 + dj;
            const float w = __shfl_sync(0xffffffffu, sv[j >> 2],
                                        lanebase | (j & 3));
            const float4 v0 = *(const float4*)(vrow + dj * KP);
            const float4 v1 = *(const float4*)(vrow + dj * KP + 4);
            a0.x = fmaf(w, v0.x, a0.x); a0.y = fmaf(w, v0.y, a0.y);
            a0.z = fmaf(w, v0.z, a0.z); a0.w = fmaf(w, v0.w, a0.w);
            a1.x = fmaf(w, v1.x, a1.x); a1.y = fmaf(w, v1.y, a1.y);
            a1.z = fmaf(w, v1.z, a1.z); a1.w = fmaf(w, v1.w, a1.w);
        }
    }
    // tf32-RNA-round output so the proj GEMM's in-register rounding is a no-op
    a0.x = tfr(a0.x); a0.y = tfr(a0.y); a0.z = tfr(a0.z); a0.w = tfr(a0.w);
    a1.x = tfr(a1.x); a1.y = tfr(a1.y); a1.z = tfr(a1.z); a1.w = tfr(a1.w);
    float* op = out + qpix * CC + head * HD + g * 8;
    *(float4*)op = a0;
    *(float4*)(op + 4) = a1;
}

// ---------------------------------------------------------------------------
extern "C" void kernel_launch(void* const* d_in, const int* in_sizes, int n_in,
                              void* d_out, int out_size)
{
    (void)in_sizes; (void)n_in; (void)out_size;
    const float* x      = (const float*)d_in[0];
    const float* w_qkv  = (const float*)d_in[1];
    const float* b_qkv  = (const float*)d_in[2];
    const float* rpb    = (const float*)d_in[3];
    const float* w_proj = (const float*)d_in[4];
    const float* b_proj = (const float*)d_in[5];
    float* out = (float*)d_out;

    float *qkvb = nullptr, *attnb = nullptr;
    cudaGetSymbolAddress((void**)&qkvb, g_qkv);
    cudaGetSymbolAddress((void**)&attnb, g_attn);

    cudaFuncSetAttribute(tgemm_ca, cudaFuncAttributeMaxDynamicSharedMemorySize,
                         GEMM_SMEM);
    cudaFuncSetAttribute(na2d_attn, cudaFuncAttributeMaxDynamicSharedMemorySize,
                         ATTN_SMEM_BYTES);

    const float qscale = 0.17677669529663689f; // 32^-0.5

    // 1) qkv = x @ w_qkv + b_qkv  (q columns pre-scaled); no prep needed
    tgemm_ca<<<dim3(QKV_N / 64, M_TOTAL / 128), 256, GEMM_SMEM>>>(
        x, w_qkv, b_qkv, qkvb, QKV_N, 256, qscale);

    // 2) neighborhood attention (natural [M][C] tf32 output)
    na2d_attn<<<dim3(49, NHEAD, BATCH), 256, ATTN_SMEM_BYTES>>>(qkvb, rpb, attnb);

    // 3) out = attn @ w_proj + b_proj
    tgemm_ca<<<dim3(CC / 64, M_TOTAL / 128), 256, GEMM_SMEM>>>(
        attnb, w_proj, b_proj, out, CC, 0, 1.f);
}

// round 11
// speedup vs baseline: 1.2195x; 1.0169x over previous
#include <cuda_runtime.h>
#include <cuda_bf16.h>
#include <math.h>
#include <stdint.h>

// Problem constants
#define BATCH 4
#define HH 56
#define WW 56
#define CC 256
#define NHEAD 8
#define HD 32
#define KS 7
#define PADR 3
#define M_TOTAL (BATCH * HH * WW)   // 12544
#define QKV_N (3 * CC)              // 768
#define GK 256                      // K of both GEMMs

// Scratch (device globals: allocation-free rule)
__device__ float g_qkv[M_TOTAL * QKV_N];   // [pix][768] q|k|v, q pre-scaled
__device__ float g_attn[M_TOTAL * CC];     // attention out [M][C], tf32-rounded

__device__ __forceinline__ unsigned f2tf32(float x) {
    unsigned r;
    asm("cvt.rna.tf32.f32 %0, %1;" : "=r"(r) : "f"(x));
    return r;
}
__device__ __forceinline__ float tfr(float x) {
    return __uint_as_float(f2tf32(x));
}
__device__ __forceinline__ uint32_t smem_u32(const void* p) {
    uint32_t a;
    asm("{ .reg .u64 t; cvta.to.shared.u64 t, %1; cvt.u32.u64 %0, t; }"
        : "=r"(a) : "l"(p));
    return a;
}
__device__ __forceinline__ void cp16(uint32_t dst, const void* src) {
    asm volatile("cp.async.cg.shared.global [%0], [%1], 16;\n"
                 :: "r"(dst), "l"(src));
}
#define CP_COMMIT() asm volatile("cp.async.commit_group;\n" ::: "memory")
#define CP_WAIT1()  asm volatile("cp.async.wait_group 1;\n" ::: "memory")

// ---------------------------------------------------------------------------
// cp.async 3-stage TF32 GEMM, raw fp32 inputs (RNA->tf32 in-register).
// A [M][K=256] row-major, B [K=256][N] row-major. C[M][N] = A @ B + bias.
// Block tile 128x128x32, 256 thr = 8 warps (4Mx2N), warp tile 32x64,
// mma.m16n8k8. A smem [m][k] pitch 36 (lane bank 4*qr+t, conflict-free);
// B smem [k][n] pitch 136 (lane bank 8*t+qr, conflict-free).
// 3 stages = 105KB, 2 blocks/SM, 2-tile cp.async lookahead.
// ---------------------------------------------------------------------------
#define NSTAGE 3
#define A_PITCH 36                     // floats per A row (32 + 4 pad)
#define B_PITCH 136                    // floats per B row (128 + 8 pad)
#define ASTG_B (128 * A_PITCH * 4)     // 18432
#define BSTG_B (32 * B_PITCH * 4)      // 17408
#define STG_B  (ASTG_B + BSTG_B)       // 35840
#define GEMM_SMEM (NSTAGE * STG_B)     // 107520

__device__ __forceinline__ void mma_tf32(float4& d,
    unsigned a0, unsigned a1, unsigned a2, unsigned a3,
    unsigned b0, unsigned b1)
{
    asm volatile(
        "mma.sync.aligned.m16n8k8.row.col.f32.tf32.tf32.f32 "
        "{%0,%1,%2,%3},{%4,%5,%6,%7},{%8,%9},{%0,%1,%2,%3};\n"
        : "+f"(d.x), "+f"(d.y), "+f"(d.z), "+f"(d.w)
        : "r"(a0), "r"(a1), "r"(a2), "r"(a3), "r"(b0), "r"(b1));
}

__global__ __launch_bounds__(256, 2) void tgemm_ca(
    const float* __restrict__ A, const float* __restrict__ B,
    const float* __restrict__ bias, float* __restrict__ C,
    int N, int scaleCols, float scale)
{
    extern __shared__ float sm[];
    const uint32_t sb = smem_u32(sm);
    const int tid  = threadIdx.x;
    const int wid  = tid >> 5;
    const int lane = tid & 31;
    const int warp_m = wid & 3;        // 4 warps along M (32 rows)
    const int warp_n = wid >> 2;       // 2 warps along N (64 cols)
    const int t  = lane & 3;           // k within quad
    const int qr = lane >> 2;          // group row 0..7
    const int bm = blockIdx.y << 7;
    const int bn = blockIdx.x << 7;

    // A load: base row lr (0..31), rows lr+32e (e=0..3), chunk lc in 128B row
    const int lr = tid >> 3;
    const int lc = tid & 7;
    const float* Asrc = A + (size_t)(bm + lr) * GK + lc * 4;
    const uint32_t aOff = (uint32_t)(lr * A_PITCH + lc * 4) * 4u;
    // B load: k-row lr (0..31), col chunks lc*4 + 32e (e=0..3)
    const float* Bsrc = B + (size_t)lr * N + bn + lc * 4;
    const uint32_t bOff = (uint32_t)ASTG_B + (uint32_t)(lr * B_PITCH + lc * 4) * 4u;

    float acc[2][8][4];
    #pragma unroll
    for (int mt = 0; mt < 2; ++mt)
        #pragma unroll
        for (int nt = 0; nt < 8; ++nt)
            #pragma unroll
            for (int i = 0; i < 4; ++i) acc[mt][nt][i] = 0.f;

    // prologue: stages 0,1 <- k-tiles 0,1
    #pragma unroll
    for (int s = 0; s < NSTAGE - 1; ++s) {
        const uint32_t sd = sb + s * STG_B;
        #pragma unroll
        for (int e = 0; e < 4; ++e)
            cp16(sd + aOff + e * (32u * A_PITCH * 4u),
                 Asrc + (size_t)e * 32 * GK + s * 32);
        #pragma unroll
        for (int e = 0; e < 4; ++e)
            cp16(sd + bOff + e * 128u, Bsrc + (size_t)s * 32 * N + e * 32);
        CP_COMMIT();
    }

    int stage = 0;   // stage holding tile kt
    #pragma unroll 1
    for (int kt = 0; kt < 8; ++kt) {
        CP_WAIT1();          // all but newest group complete -> tile kt resident
        __syncthreads();

        if (kt + 2 < 8) {
            const int ls = (stage + 2 >= NSTAGE) ? stage + 2 - NSTAGE : stage + 2;
            const uint32_t sd = sb + ls * STG_B;
            #pragma unroll
            for (int e = 0; e < 4; ++e)
                cp16(sd + aOff + e * (32u * A_PITCH * 4u),
                     Asrc + (size_t)e * 32 * GK + (kt + 2) * 32);
            #pragma unroll
            for (int e = 0; e < 4; ++e)
                cp16(sd + bOff + e * 128u, Bsrc + (size_t)(kt + 2) * 32 * N + e * 32);
        }
        CP_COMMIT();         // always commit (keeps wait_group arithmetic exact)

        const float* as = sm + stage * (STG_B / 4) + (warp_m * 32) * A_PITCH;
        const float* bs = sm + stage * (STG_B / 4) + (ASTG_B / 4)
                          + warp_n * 64 + qr;
        #pragma unroll
        for (int ss = 0; ss < 4; ++ss) {
            const int kk = ss * 8 + t;
            const float* ap = as + kk;
            const float* bp = bs + kk * B_PITCH;
            unsigned a0[2], a1[2], a2[2], a3[2];
            #pragma unroll
            for (int mt = 0; mt < 2; ++mt) {
                a0[mt] = f2tf32(ap[(mt * 16 + qr) * A_PITCH]);
                a1[mt] = f2tf32(ap[(mt * 16 + qr + 8) * A_PITCH]);
                a2[mt] = f2tf32(ap[(mt * 16 + qr) * A_PITCH + 4]);
                a3[mt] = f2tf32(ap[(mt * 16 + qr + 8) * A_PITCH + 4]);
            }
            unsigned b0[8], b1[8];
            #pragma unroll
            for (int nt = 0; nt < 8; ++nt) {
                b0[nt] = f2tf32(bp[nt * 8]);
                b1[nt] = f2tf32(bp[nt * 8 + 4 * B_PITCH]);
            }
            #pragma unroll
            for (int mt = 0; mt < 2; ++mt)
                #pragma unroll
                for (int nt = 0; nt < 8; ++nt)
                    mma_tf32(*(float4*)acc[mt][nt],
                             a0[mt], a1[mt], a2[mt], a3[mt],
                             b0[nt], b1[nt]);
        }
        stage = (stage + 1 >= NSTAGE) ? 0 : stage + 1;
    }

    const float sc = (bn < scaleCols) ? scale : 1.f;
    #pragma unroll
    for (int nt = 0; nt < 8; ++nt) {
        const int gn = bn + warp_n * 64 + nt * 8 + 2 * t;
        const float2 bz = *(const float2*)&bias[gn];
        #pragma unroll
        for (int mt = 0; mt < 2; ++mt) {
            const int gm = bm + warp_m * 32 + mt * 16 + qr;
            float2 r0, r1;
            r0.x = (acc[mt][nt][0] + bz.x) * sc;
            r0.y = (acc[mt][nt][1] + bz.y) * sc;
            r1.x = (acc[mt][nt][2] + bz.x) * sc;
            r1.y = (acc[mt][nt][3] + bz.y) * sc;
            *(float2*)&C[(size_t)gm * N + gn] = r0;
            *(float2*)&C[(size_t)(gm + 8) * N + gn] = r1;
        }
    }
}

// ---------------------------------------------------------------------------
// Neighborhood attention (unchanged from round 10, the proven body).
// ---------------------------------------------------------------------------
#define TQ 8
#define WIN 14
#define KP 36
#define ATTN_SMEM_FLOATS (2 * WIN * WIN * KP + 52)
#define ATTN_SMEM_BYTES (ATTN_SMEM_FLOATS * 4)

__global__ __launch_bounds__(256) void na2d_attn(
    const float* __restrict__ qkv, const float* __restrict__ rpb,
    float* __restrict__ out)
{
    extern __shared__ float sm[];
    float* ks_  = sm;
    float* vs_  = sm + WIN * WIN * KP;
    float* rpbs = sm + 2 * WIN * WIN * KP;

    const int b    = blockIdx.z;
    const int head = blockIdx.y;
    const int tY   = blockIdx.x / 7;
    const int tX   = blockIdx.x - tY * 7;
    const int oy   = tY * TQ;
    const int ox   = tX * TQ;
    const int tid  = threadIdx.x;

    if (tid < 49) rpbs[tid] = rpb[head * 49 + tid];
    const bool interior = (tY >= 1) && (tY <= 5) && (tX >= 1) && (tX <= 5);
    if (interior) {
        #pragma unroll 1
        for (int idx = tid; idx < WIN * WIN * 8; idx += 256) {
            const int row = idx >> 3;
            const int d4  = idx & 7;
            const int wy = row / WIN, wx = row - wy * WIN;
            const int gy = oy - PADR + wy, gx = ox - PADR + wx;
            const float* p = qkv + (size_t)(((b * HH + gy) * WW) + gx) * QKV_N
                           + head * HD + d4 * 4;
            *(float4*)&ks_[row * KP + d4 * 4] = *(const float4*)(p + 256);
            *(float4*)&vs_[row * KP + d4 * 4] = *(const float4*)(p + 512);
        }
    } else {
        #pragma unroll 1
        for (int idx = tid; idx < WIN * WIN * 8; idx += 256) {
            const int row = idx >> 3;
            const int d4  = idx & 7;
            const int wy = row / WIN, wx = row - wy * WIN;
            const int gy = oy - PADR + wy, gx = ox - PADR + wx;
            float4 kv = make_float4(0.f, 0.f, 0.f, 0.f);
            float4 vv = make_float4(0.f, 0.f, 0.f, 0.f);
            if (gy >= 0 && gy < HH && gx >= 0 && gx < WW) {
                const float* p = qkv + (size_t)(((b * HH + gy) * WW) + gx) * QKV_N
                               + head * HD + d4 * 4;
                kv = *(const float4*)(p + 256);
                vv = *(const float4*)(p + 512);
            }
            *(float4*)&ks_[row * KP + d4 * 4] = kv;
            *(float4*)&vs_[row * KP + d4 * 4] = vv;
        }
    }

    const int qi = tid >> 2;
    const int g  = tid & 3;
    const int qy = qi >> 3, qx = qi & 7;
    const size_t qpix = (size_t)((b * HH + oy + qy) * WW) + ox + qx;
    const float4* qp = (const float4*)(qkv + qpix * QKV_N + head * HD);
    float4 qv[8];
    #pragma unroll
    for (int cc = 0; cc < 8; ++cc) qv[cc] = qp[cc];

    __syncthreads();

    float sv[13];
    #pragma unroll
    for (int u = 0; u < 13; ++u) {
        const int j = g + 4 * u;
        const bool act = (j < 49);
        const int jc = act ? j : 48;
        const int di = jc / 7, dj = jc - di * 7;
        const float4* kr = (const float4*)(ks_ + ((qy + di) * WIN + qx + dj) * KP);
        float s0 = 0.f, s1 = 0.f, s2 = 0.f, s3 = 0.f;
        #pragma unroll
        for (int cc = 0; cc < 8; cc += 2) {
            const float4 k0 = kr[cc], k1 = kr[cc + 1];
            s0 = fmaf(qv[cc].x, k0.x, s0);
            s1 = fmaf(qv[cc].y, k0.y, s1);
            s2 = fmaf(qv[cc].z, k0.z, s2);
            s3 = fmaf(qv[cc].w, k0.w, s3);
            s0 = fmaf(qv[cc+1].x, k1.x, s0);
            s1 = fmaf(qv[cc+1].y, k1.y, s1);
            s2 = fmaf(qv[cc+1].z, k1.z, s2);
            s3 = fmaf(qv[cc+1].w, k1.w, s3);
        }
        sv[u] = act ? ((s0 + s1) + (s2 + s3) + rpbs[jc]) : -1e30f;
    }

    float m = sv[0];
    #pragma unroll
    for (int u = 1; u < 13; ++u) m = fmaxf(m, sv[u]);
    m = fmaxf(m, __shfl_xor_sync(0xffffffffu, m, 1));
    m = fmaxf(m, __shfl_xor_sync(0xffffffffu, m, 2));
    float ssum = 0.f;
    #pragma unroll
    for (int u = 0; u < 13; ++u) {
        const float e = __expf(sv[u] - m);
        sv[u] = e;
        ssum += e;
    }
    ssum += __shfl_xor_sync(0xffffffffu, ssum, 1);
    ssum += __shfl_xor_sync(0xffffffffu, ssum, 2);
    const float inv = 1.f / ssum;
    #pragma unroll
    for (int u = 0; u < 13; ++u) sv[u] *= inv;

    const int lanebase = (tid & 31) & ~3;
    float4 a0 = make_float4(0.f, 0.f, 0.f, 0.f);
    float4 a1 = make_float4(0.f, 0.f, 0.f, 0.f);
    #pragma unroll
    for (int di = 0; di < 7; ++di) {
        const float* vrow = vs_ + ((qy + di) * WIN + qx) * KP + g * 8;
        #pragma unroll
        for (int dj = 0; dj < 7; ++dj) {
            const int j = di * 7 + dj;
            const float w = __shfl_sync(0xffffffffu, sv[j >> 2],
                                        lanebase | (j & 3));
            const float4 v0 = *(const float4*)(vrow + dj * KP);
            const float4 v1 = *(const float4*)(vrow + dj * KP + 4);
            a0.x = fmaf(w, v0.x, a0.x); a0.y = fmaf(w, v0.y, a0.y);
            a0.z = fmaf(w, v0.z, a0.z); a0.w = fmaf(w, v0.w, a0.w);
            a1.x = fmaf(w, v1.x, a1.x); a1.y = fmaf(w, v1.y, a1.y);
            a1.z = fmaf(w, v1.z, a1.z); a1.w = fmaf(w, v1.w, a1.w);
        }
    }
    // tf32-RNA-round output so the proj GEMM's in-register rounding is a no-op
    a0.x = tfr(a0.x); a0.y = tfr(a0.y); a0.z = tfr(a0.z); a0.w = tfr(a0.w);
    a1.x = tfr(a1.x); a1.y = tfr(a1.y); a1.z = tfr(a1.z); a1.w = tfr(a1.w);
    float* op = out + qpix * CC + head * HD + g * 8;
    *(float4*)op = a0;
    *(float4*)(op + 4) = a1;
}

// ---------------------------------------------------------------------------
extern "C" void kernel_launch(void* const* d_in, const int* in_sizes, int n_in,
                              void* d_out, int out_size)
{
    (void)in_sizes; (void)n_in; (void)out_size;
    const float* x      = (const float*)d_in[0];
    const float* w_qkv  = (const float*)d_in[1];
    const float* b_qkv  = (const float*)d_in[2];
    const float* rpb    = (const float*)d_in[3];
    const float* w_proj = (const float*)d_in[4];
    const float* b_proj = (const float*)d_in[5];
    float* out = (float*)d_out;

    float *qkvb = nullptr, *attnb = nullptr;
    cudaGetSymbolAddress((void**)&qkvb, g_qkv);
    cudaGetSymbolAddress((void**)&attnb, g_attn);

    cudaFuncSetAttribute(tgemm_ca, cudaFuncAttributeMaxDynamicSharedMemorySize,
                         GEMM_SMEM);
    cudaFuncSetAttribute(na2d_attn, cudaFuncAttributeMaxDynamicSharedMemorySize,
                         ATTN_SMEM_BYTES);

    const float qscale = 0.17677669529663689f; // 32^-0.5

    // 1) qkv = x @ w_qkv + b_qkv  (q columns pre-scaled)
    tgemm_ca<<<dim3(QKV_N / 128, M_TOTAL / 128), 256, GEMM_SMEM>>>(
        x, w_qkv, b_qkv, qkvb, QKV_N, 256, qscale);

    // 2) neighborhood attention ([M][C] tf32 output)
    na2d_attn<<<dim3(49, NHEAD, BATCH), 256, ATTN_SMEM_BYTES>>>(qkvb, rpb, attnb);

    // 3) out = attn @ w_proj + b_proj
    tgemm_ca<<<dim3(CC / 128, M_TOTAL / 128), 256, GEMM_SMEM>>>(
        attnb, w_proj, b_proj, out, CC, 0, 1.f);
}

// round 12
// speedup vs baseline: 1.3160x; 1.0791x over previous
#include <cuda_runtime.h>
#include <cuda_bf16.h>
#include <cuda_fp16.h>
#include <math.h>
#include <stdint.h>

// Problem constants
#define BATCH 4
#define HH 56
#define WW 56
#define CC 256
#define NHEAD 8
#define HD 32
#define KS 7
#define PADR 3
#define M_TOTAL (BATCH * HH * WW)   // 12544
#define QKV_N (3 * CC)              // 768
#define GK 256                      // K of both GEMMs

// Scratch (device globals: allocation-free rule)
__device__ float g_qkv[M_TOTAL * QKV_N];   // [pix][768] q|k|v, q pre-scaled
__device__ float g_attn[M_TOTAL * CC];     // attention out [M][C], tf32-rounded

__device__ __forceinline__ unsigned f2tf32(float x) {
    unsigned r;
    asm("cvt.rna.tf32.f32 %0, %1;" : "=r"(r) : "f"(x));
    return r;
}
__device__ __forceinline__ float tfr(float x) {
    return __uint_as_float(f2tf32(x));
}
__device__ __forceinline__ uint32_t smem_u32(const void* p) {
    uint32_t a;
    asm("{ .reg .u64 t; cvta.to.shared.u64 t, %1; cvt.u32.u64 %0, t; }"
        : "=r"(a) : "l"(p));
    return a;
}
__device__ __forceinline__ void cp16(uint32_t dst, const void* src) {
    asm volatile("cp.async.cg.shared.global [%0], [%1], 16;\n"
                 :: "r"(dst), "l"(src));
}
#define CP_COMMIT() asm volatile("cp.async.commit_group;\n" ::: "memory")
#define CP_WAIT1()  asm volatile("cp.async.wait_group 1;\n" ::: "memory")

__device__ __forceinline__ unsigned h2u(__half2 h) {
    return *reinterpret_cast<unsigned*>(&h);
}
__device__ __forceinline__ __half2 u2h(unsigned u) {
    return *reinterpret_cast<__half2*>(&u);
}

// ---------------------------------------------------------------------------
// cp.async 3-stage TF32 GEMM (unchanged from round 11).
// ---------------------------------------------------------------------------
#define NSTAGE 3
#define A_PITCH 36
#define B_PITCH 136
#define ASTG_B (128 * A_PITCH * 4)     // 18432
#define BSTG_B (32 * B_PITCH * 4)      // 17408
#define STG_B  (ASTG_B + BSTG_B)       // 35840
#define GEMM_SMEM (NSTAGE * STG_B)     // 107520

__device__ __forceinline__ void mma_tf32(float4& d,
    unsigned a0, unsigned a1, unsigned a2, unsigned a3,
    unsigned b0, unsigned b1)
{
    asm volatile(
        "mma.sync.aligned.m16n8k8.row.col.f32.tf32.tf32.f32 "
        "{%0,%1,%2,%3},{%4,%5,%6,%7},{%8,%9},{%0,%1,%2,%3};\n"
        : "+f"(d.x), "+f"(d.y), "+f"(d.z), "+f"(d.w)
        : "r"(a0), "r"(a1), "r"(a2), "r"(a3), "r"(b0), "r"(b1));
}

__global__ __launch_bounds__(256, 2) void tgemm_ca(
    const float* __restrict__ A, const float* __restrict__ B,
    const float* __restrict__ bias, float* __restrict__ C,
    int N, int scaleCols, float scale)
{
    extern __shared__ float sm[];
    const uint32_t sb = smem_u32(sm);
    const int tid  = threadIdx.x;
    const int wid  = tid >> 5;
    const int lane = tid & 31;
    const int warp_m = wid & 3;
    const int warp_n = wid >> 2;
    const int t  = lane & 3;
    const int qr = lane >> 2;
    const int bm = blockIdx.y << 7;
    const int bn = blockIdx.x << 7;

    const int lr = tid >> 3;
    const int lc = tid & 7;
    const float* Asrc = A + (size_t)(bm + lr) * GK + lc * 4;
    const uint32_t aOff = (uint32_t)(lr * A_PITCH + lc * 4) * 4u;
    const float* Bsrc = B + (size_t)lr * N + bn + lc * 4;
    const uint32_t bOff = (uint32_t)ASTG_B + (uint32_t)(lr * B_PITCH + lc * 4) * 4u;

    float acc[2][8][4];
    #pragma unroll
    for (int mt = 0; mt < 2; ++mt)
        #pragma unroll
        for (int nt = 0; nt < 8; ++nt)
            #pragma unroll
            for (int i = 0; i < 4; ++i) acc[mt][nt][i] = 0.f;

    #pragma unroll
    for (int s = 0; s < NSTAGE - 1; ++s) {
        const uint32_t sd = sb + s * STG_B;
        #pragma unroll
        for (int e = 0; e < 4; ++e)
            cp16(sd + aOff + e * (32u * A_PITCH * 4u),
                 Asrc + (size_t)e * 32 * GK + s * 32);
        #pragma unroll
        for (int e = 0; e < 4; ++e)
            cp16(sd + bOff + e * 128u, Bsrc + (size_t)s * 32 * N + e * 32);
        CP_COMMIT();
    }

    int stage = 0;
    #pragma unroll 1
    for (int kt = 0; kt < 8; ++kt) {
        CP_WAIT1();
        __syncthreads();

        if (kt + 2 < 8) {
            const int ls = (stage + 2 >= NSTAGE) ? stage + 2 - NSTAGE : stage + 2;
            const uint32_t sd = sb + ls * STG_B;
            #pragma unroll
            for (int e = 0; e < 4; ++e)
                cp16(sd + aOff + e * (32u * A_PITCH * 4u),
                     Asrc + (size_t)e * 32 * GK + (kt + 2) * 32);
            #pragma unroll
            for (int e = 0; e < 4; ++e)
                cp16(sd + bOff + e * 128u, Bsrc + (size_t)(kt + 2) * 32 * N + e * 32);
        }
        CP_COMMIT();

        const float* as = sm + stage * (STG_B / 4) + (warp_m * 32) * A_PITCH;
        const float* bs = sm + stage * (STG_B / 4) + (ASTG_B / 4)
                          + warp_n * 64 + qr;
        #pragma unroll
        for (int ss = 0; ss < 4; ++ss) {
            const int kk = ss * 8 + t;
            const float* ap = as + kk;
            const float* bp = bs + kk * B_PITCH;
            unsigned a0[2], a1[2], a2[2], a3[2];
            #pragma unroll
            for (int mt = 0; mt < 2; ++mt) {
                a0[mt] = f2tf32(ap[(mt * 16 + qr) * A_PITCH]);
                a1[mt] = f2tf32(ap[(mt * 16 + qr + 8) * A_PITCH]);
                a2[mt] = f2tf32(ap[(mt * 16 + qr) * A_PITCH + 4]);
                a3[mt] = f2tf32(ap[(mt * 16 + qr + 8) * A_PITCH + 4]);
            }
            unsigned b0[8], b1[8];
            #pragma unroll
            for (int nt = 0; nt < 8; ++nt) {
                b0[nt] = f2tf32(bp[nt * 8]);
                b1[nt] = f2tf32(bp[nt * 8 + 4 * B_PITCH]);
            }
            #pragma unroll
            for (int mt = 0; mt < 2; ++mt)
                #pragma unroll
                for (int nt = 0; nt < 8; ++nt)
                    mma_tf32(*(float4*)acc[mt][nt],
                             a0[mt], a1[mt], a2[mt], a3[mt],
                             b0[nt], b1[nt]);
        }
        stage = (stage + 1 >= NSTAGE) ? 0 : stage + 1;
    }

    const float sc = (bn < scaleCols) ? scale : 1.f;
    #pragma unroll
    for (int nt = 0; nt < 8; ++nt) {
        const int gn = bn + warp_n * 64 + nt * 8 + 2 * t;
        const float2 bz = *(const float2*)&bias[gn];
        #pragma unroll
        for (int mt = 0; mt < 2; ++mt) {
            const int gm = bm + warp_m * 32 + mt * 16 + qr;
            float2 r0, r1;
            r0.x = (acc[mt][nt][0] + bz.x) * sc;
            r0.y = (acc[mt][nt][1] + bz.y) * sc;
            r1.x = (acc[mt][nt][2] + bz.x) * sc;
            r1.y = (acc[mt][nt][3] + bz.y) * sc;
            *(float2*)&C[(size_t)gm * N + gn] = r0;
            *(float2*)&C[(size_t)(gm + 8) * N + gn] = r1;
        }
    }
}

// ---------------------------------------------------------------------------
// Neighborhood attention with fp16 k/v in smem (fp32 math).
// k: row-major, 196 rows x 56 halfs (112B pitch = 7 chunks; QK conflicts only
//    when drow % 8 == 0 -> rare). v: 4 dim-chunk planes, plane stride 197
//    chunks -> AV lane chunk = 5g + row (mod 8): conflict-free.
// Scores/softmax in fp32 registers (quad shfl), weights broadcast by shfl.
// ---------------------------------------------------------------------------
#define TQ 8
#define WIN 14
#define KPH 56                        // halfs per k row (32 data + 24 pad)
#define K_BYTES (196 * 112)           // 21952
#define VPLANE 1576                   // halfs per v plane (197 * 8)
#define V_BYTES (4 * VPLANE * 2)      // 12608
#define ATTN_SMEM_BYTES (K_BYTES + V_BYTES + 256)   // 34816

__global__ __launch_bounds__(256) void na2d_attn(
    const float* __restrict__ qkv, const float* __restrict__ rpb,
    float* __restrict__ out)
{
    extern __shared__ float sm[];
    __half* ks_h = (__half*)sm;
    __half* vs_h = (__half*)((char*)sm + K_BYTES);
    float*  rpbs = (float*)((char*)sm + K_BYTES + V_BYTES);

    const int b    = blockIdx.z;
    const int head = blockIdx.y;
    const int tY   = blockIdx.x / 7;
    const int tX   = blockIdx.x - tY * 7;
    const int oy   = tY * TQ;
    const int ox   = tX * TQ;
    const int tid  = threadIdx.x;

    if (tid < 49) rpbs[tid] = rpb[head * 49 + tid];

    // --- load 14x14 k/v window, convert to fp16 ---
    // idx -> (row, c): row 0..195, c 0..3 (16B chunk of 8 halfs = dims 8c..8c+7)
    const bool interior = (tY >= 1) && (tY <= 5) && (tX >= 1) && (tX <= 5);
    #pragma unroll 1
    for (int idx = tid; idx < 196 * 4; idx += 256) {
        const int row = idx >> 2;
        const int c   = idx & 3;
        const int wy = row / WIN, wx = row - wy * WIN;
        const int gy = oy - PADR + wy, gx = ox - PADR + wx;
        uint4 kk = make_uint4(0, 0, 0, 0);
        uint4 vv = make_uint4(0, 0, 0, 0);
        if (interior || (gy >= 0 && gy < HH && gx >= 0 && gx < WW)) {
            const float* p = qkv + (size_t)(((b * HH + gy) * WW) + gx) * QKV_N
                           + head * HD + c * 8;
            const float4 k0 = *(const float4*)(p + 256);
            const float4 k1 = *(const float4*)(p + 260);
            const float4 v0 = *(const float4*)(p + 512);
            const float4 v1 = *(const float4*)(p + 516);
            kk.x = h2u(__float22half2_rn(make_float2(k0.x, k0.y)));
            kk.y = h2u(__float22half2_rn(make_float2(k0.z, k0.w)));
            kk.z = h2u(__float22half2_rn(make_float2(k1.x, k1.y)));
            kk.w = h2u(__float22half2_rn(make_float2(k1.z, k1.w)));
            vv.x = h2u(__float22half2_rn(make_float2(v0.x, v0.y)));
            vv.y = h2u(__float22half2_rn(make_float2(v0.z, v0.w)));
            vv.z = h2u(__float22half2_rn(make_float2(v1.x, v1.y)));
            vv.w = h2u(__float22half2_rn(make_float2(v1.z, v1.w)));
        }
        *(uint4*)(ks_h + row * KPH + c * 8) = kk;        // byte: row*112 + c*16
        *(uint4*)(vs_h + c * VPLANE + row * 8) = vv;     // byte: c*3152 + row*16
    }

    // --- q into fp32 registers (4 threads per query share the same q) ---
    const int qi = tid >> 2;
    const int g  = tid & 3;
    const int qy = qi >> 3, qx = qi & 7;
    const size_t qpix = (size_t)((b * HH + oy + qy) * WW) + ox + qx;
    const float4* qp = (const float4*)(qkv + qpix * QKV_N + head * HD);
    float4 qv[8];
    #pragma unroll
    for (int cc = 0; cc < 8; ++cc) qv[cc] = qp[cc];

    __syncthreads();

    // --- phase 1: scores in fp32 registers (thread owns j = g + 4u) ---
    float sv[13];
    #pragma unroll
    for (int u = 0; u < 13; ++u) {
        const int j = g + 4 * u;
        const bool act = (j < 49);
        const int jc = act ? j : 48;
        const int di = jc / 7, dj = jc - di * 7;
        const int row = (qy + di) * WIN + qx + dj;
        const uint4* kr = (const uint4*)(ks_h + row * KPH);
        float s0 = 0.f, s1 = 0.f, s2 = 0.f, s3 = 0.f;
        #pragma unroll
        for (int c = 0; c < 4; ++c) {
            const uint4 kk = kr[c];
            const float2 f0 = __half22float2(u2h(kk.x));
            const float2 f1 = __half22float2(u2h(kk.y));
            const float2 f2 = __half22float2(u2h(kk.z));
            const float2 f3 = __half22float2(u2h(kk.w));
            const float4 qa = qv[2 * c];
            const float4 qb = qv[2 * c + 1];
            s0 = fmaf(qa.x, f0.x, s0);
            s1 = fmaf(qa.y, f0.y, s1);
            s2 = fmaf(qa.z, f1.x, s2);
            s3 = fmaf(qa.w, f1.y, s3);
            s0 = fmaf(qb.x, f2.x, s0);
            s1 = fmaf(qb.y, f2.y, s1);
            s2 = fmaf(qb.z, f3.x, s2);
            s3 = fmaf(qb.w, f3.y, s3);
        }
        sv[u] = act ? ((s0 + s1) + (s2 + s3) + rpbs[jc]) : -1e30f;
    }

    // --- softmax across quad; weights stay in registers ---
    float m = sv[0];
    #pragma unroll
    for (int u = 1; u < 13; ++u) m = fmaxf(m, sv[u]);
    m = fmaxf(m, __shfl_xor_sync(0xffffffffu, m, 1));
    m = fmaxf(m, __shfl_xor_sync(0xffffffffu, m, 2));
    float ssum = 0.f;
    #pragma unroll
    for (int u = 0; u < 13; ++u) {
        const float e = __expf(sv[u] - m);
        sv[u] = e;
        ssum += e;
    }
    ssum += __shfl_xor_sync(0xffffffffu, ssum, 1);
    ssum += __shfl_xor_sync(0xffffffffu, ssum, 2);
    const float inv = 1.f / ssum;
    #pragma unroll
    for (int u = 0; u < 13; ++u) sv[u] *= inv;

    // --- phase 3: AV. thread g reads v plane g (dims 8g..8g+7) ---
    const int lanebase = (tid & 31) & ~3;
    const __half* vbase = vs_h + g * VPLANE;
    float4 a0 = make_float4(0.f, 0.f, 0.f, 0.f);
    float4 a1 = make_float4(0.f, 0.f, 0.f, 0.f);
    #pragma unroll
    for (int di = 0; di < 7; ++di) {
        const int rbase = (qy + di) * WIN + qx;
        #pragma unroll
        for (int dj = 0; dj < 7; ++dj) {
            const int j = di * 7 + dj;
            const float w = __shfl_sync(0xffffffffu, sv[j >> 2],
                                        lanebase | (j & 3));
            const uint4 vv = *(const uint4*)(vbase + (rbase + dj) * 8);
            const float2 f0 = __half22float2(u2h(vv.x));
            const float2 f1 = __half22float2(u2h(vv.y));
            const float2 f2 = __half22float2(u2h(vv.z));
            const float2 f3 = __half22float2(u2h(vv.w));
            a0.x = fmaf(w, f0.x, a0.x); a0.y = fmaf(w, f0.y, a0.y);
            a0.z = fmaf(w, f1.x, a0.z); a0.w = fmaf(w, f1.y, a0.w);
            a1.x = fmaf(w, f2.x, a1.x); a1.y = fmaf(w, f2.y, a1.y);
            a1.z = fmaf(w, f3.x, a1.z); a1.w = fmaf(w, f3.y, a1.w);
        }
    }
    // tf32-RNA-round output so the proj GEMM's in-register rounding is a no-op
    a0.x = tfr(a0.x); a0.y = tfr(a0.y); a0.z = tfr(a0.z); a0.w = tfr(a0.w);
    a1.x = tfr(a1.x); a1.y = tfr(a1.y); a1.z = tfr(a1.z); a1.w = tfr(a1.w);
    float* op = out + qpix * CC + head * HD + g * 8;
    *(float4*)op = a0;
    *(float4*)(op + 4) = a1;
}

// ---------------------------------------------------------------------------
extern "C" void kernel_launch(void* const* d_in, const int* in_sizes, int n_in,
                              void* d_out, int out_size)
{
    (void)in_sizes; (void)n_in; (void)out_size;
    const float* x      = (const float*)d_in[0];
    const float* w_qkv  = (const float*)d_in[1];
    const float* b_qkv  = (const float*)d_in[2];
    const float* rpb    = (const float*)d_in[3];
    const float* w_proj = (const float*)d_in[4];
    const float* b_proj = (const float*)d_in[5];
    float* out = (float*)d_out;

    float *qkvb = nullptr, *attnb = nullptr;
    cudaGetSymbolAddress((void**)&qkvb, g_qkv);
    cudaGetSymbolAddress((void**)&attnb, g_attn);

    cudaFuncSetAttribute(tgemm_ca, cudaFuncAttributeMaxDynamicSharedMemorySize,
                         GEMM_SMEM);
    cudaFuncSetAttribute(na2d_attn, cudaFuncAttributeMaxDynamicSharedMemorySize,
                         ATTN_SMEM_BYTES);

    const float qscale = 0.17677669529663689f; // 32^-0.5

    // 1) qkv = x @ w_qkv + b_qkv  (q columns pre-scaled)
    tgemm_ca<<<dim3(QKV_N / 128, M_TOTAL / 128), 256, GEMM_SMEM>>>(
        x, w_qkv, b_qkv, qkvb, QKV_N, 256, qscale);

    // 2) neighborhood attention ([M][C] tf32 output)
    na2d_attn<<<dim3(49, NHEAD, BATCH), 256, ATTN_SMEM_BYTES>>>(qkvb, rpb, attnb);

    // 3) out = attn @ w_proj + b_proj
    tgemm_ca<<<dim3(CC / 128, M_TOTAL / 128), 256, GEMM_SMEM>>>(
        attnb, w_proj, b_proj, out, CC, 0, 1.f);
}

// round 13
// speedup vs baseline: 1.3569x; 1.0311x over previous
#include <cuda_runtime.h>
#include <cuda_bf16.h>
#include <cuda_fp16.h>
#include <math.h>
#include <stdint.h>

// Problem constants
#define BATCH 4
#define HH 56
#define WW 56
#define CC 256
#define NHEAD 8
#define HD 32
#define KS 7
#define PADR 3
#define M_TOTAL (BATCH * HH * WW)   // 12544
#define QKV_N (3 * CC)              // 768
#define GK 256                      // K of both GEMMs

// Scratch (device globals: allocation-free rule)
__device__ float g_qkv[M_TOTAL * QKV_N];   // [pix][768] q|k|v, q pre-scaled
__device__ float g_attn[M_TOTAL * CC];     // attention out [M][C], tf32-rounded

__device__ __forceinline__ unsigned f2tf32(float x) {
    unsigned r;
    asm("cvt.rna.tf32.f32 %0, %1;" : "=r"(r) : "f"(x));
    return r;
}
__device__ __forceinline__ float tfr(float x) {
    return __uint_as_float(f2tf32(x));
}
__device__ __forceinline__ uint32_t smem_u32(const void* p) {
    uint32_t a;
    asm("{ .reg .u64 t; cvta.to.shared.u64 t, %1; cvt.u32.u64 %0, t; }"
        : "=r"(a) : "l"(p));
    return a;
}
__device__ __forceinline__ void cp16(uint32_t dst, const void* src) {
    asm volatile("cp.async.cg.shared.global [%0], [%1], 16;\n"
                 :: "r"(dst), "l"(src));
}
#define CP_COMMIT() asm volatile("cp.async.commit_group;\n" ::: "memory")
#define CP_WAIT1()  asm volatile("cp.async.wait_group 1;\n" ::: "memory")

__device__ __forceinline__ unsigned h2u(__half2 h) {
    return *reinterpret_cast<unsigned*>(&h);
}
__device__ __forceinline__ __half2 u2h(unsigned u) {
    return *reinterpret_cast<__half2*>(&u);
}

// ---------------------------------------------------------------------------
// cp.async 3-stage TF32 GEMM (unchanged from round 11/12).
// ---------------------------------------------------------------------------
#define NSTAGE 3
#define A_PITCH 36
#define B_PITCH 136
#define ASTG_B (128 * A_PITCH * 4)     // 18432
#define BSTG_B (32 * B_PITCH * 4)      // 17408
#define STG_B  (ASTG_B + BSTG_B)       // 35840
#define GEMM_SMEM (NSTAGE * STG_B)     // 107520

__device__ __forceinline__ void mma_tf32(float4& d,
    unsigned a0, unsigned a1, unsigned a2, unsigned a3,
    unsigned b0, unsigned b1)
{
    asm volatile(
        "mma.sync.aligned.m16n8k8.row.col.f32.tf32.tf32.f32 "
        "{%0,%1,%2,%3},{%4,%5,%6,%7},{%8,%9},{%0,%1,%2,%3};\n"
        : "+f"(d.x), "+f"(d.y), "+f"(d.z), "+f"(d.w)
        : "r"(a0), "r"(a1), "r"(a2), "r"(a3), "r"(b0), "r"(b1));
}

__global__ __launch_bounds__(256, 2) void tgemm_ca(
    const float* __restrict__ A, const float* __restrict__ B,
    const float* __restrict__ bias, float* __restrict__ C,
    int N, int scaleCols, float scale)
{
    extern __shared__ float sm[];
    const uint32_t sb = smem_u32(sm);
    const int tid  = threadIdx.x;
    const int wid  = tid >> 5;
    const int lane = tid & 31;
    const int warp_m = wid & 3;
    const int warp_n = wid >> 2;
    const int t  = lane & 3;
    const int qr = lane >> 2;
    const int bm = blockIdx.y << 7;
    const int bn = blockIdx.x << 7;

    const int lr = tid >> 3;
    const int lc = tid & 7;
    const float* Asrc = A + (size_t)(bm + lr) * GK + lc * 4;
    const uint32_t aOff = (uint32_t)(lr * A_PITCH + lc * 4) * 4u;
    const float* Bsrc = B + (size_t)lr * N + bn + lc * 4;
    const uint32_t bOff = (uint32_t)ASTG_B + (uint32_t)(lr * B_PITCH + lc * 4) * 4u;

    float acc[2][8][4];
    #pragma unroll
    for (int mt = 0; mt < 2; ++mt)
        #pragma unroll
        for (int nt = 0; nt < 8; ++nt)
            #pragma unroll
            for (int i = 0; i < 4; ++i) acc[mt][nt][i] = 0.f;

    #pragma unroll
    for (int s = 0; s < NSTAGE - 1; ++s) {
        const uint32_t sd = sb + s * STG_B;
        #pragma unroll
        for (int e = 0; e < 4; ++e)
            cp16(sd + aOff + e * (32u * A_PITCH * 4u),
                 Asrc + (size_t)e * 32 * GK + s * 32);
        #pragma unroll
        for (int e = 0; e < 4; ++e)
            cp16(sd + bOff + e * 128u, Bsrc + (size_t)s * 32 * N + e * 32);
        CP_COMMIT();
    }

    int stage = 0;
    #pragma unroll 1
    for (int kt = 0; kt < 8; ++kt) {
        CP_WAIT1();
        __syncthreads();

        if (kt + 2 < 8) {
            const int ls = (stage + 2 >= NSTAGE) ? stage + 2 - NSTAGE : stage + 2;
            const uint32_t sd = sb + ls * STG_B;
            #pragma unroll
            for (int e = 0; e < 4; ++e)
                cp16(sd + aOff + e * (32u * A_PITCH * 4u),
                     Asrc + (size_t)e * 32 * GK + (kt + 2) * 32);
            #pragma unroll
            for (int e = 0; e < 4; ++e)
                cp16(sd + bOff + e * 128u, Bsrc + (size_t)(kt + 2) * 32 * N + e * 32);
        }
        CP_COMMIT();

        const float* as = sm + stage * (STG_B / 4) + (warp_m * 32) * A_PITCH;
        const float* bs = sm + stage * (STG_B / 4) + (ASTG_B / 4)
                          + warp_n * 64 + qr;
        #pragma unroll
        for (int ss = 0; ss < 4; ++ss) {
            const int kk = ss * 8 + t;
            const float* ap = as + kk;
            const float* bp = bs + kk * B_PITCH;
            unsigned a0[2], a1[2], a2[2], a3[2];
            #pragma unroll
            for (int mt = 0; mt < 2; ++mt) {
                a0[mt] = f2tf32(ap[(mt * 16 + qr) * A_PITCH]);
                a1[mt] = f2tf32(ap[(mt * 16 + qr + 8) * A_PITCH]);
                a2[mt] = f2tf32(ap[(mt * 16 + qr) * A_PITCH + 4]);
                a3[mt] = f2tf32(ap[(mt * 16 + qr + 8) * A_PITCH + 4]);
            }
            unsigned b0[8], b1[8];
            #pragma unroll
            for (int nt = 0; nt < 8; ++nt) {
                b0[nt] = f2tf32(bp[nt * 8]);
                b1[nt] = f2tf32(bp[nt * 8 + 4 * B_PITCH]);
            }
            #pragma unroll
            for (int mt = 0; mt < 2; ++mt)
                #pragma unroll
                for (int nt = 0; nt < 8; ++nt)
                    mma_tf32(*(float4*)acc[mt][nt],
                             a0[mt], a1[mt], a2[mt], a3[mt],
                             b0[nt], b1[nt]);
        }
        stage = (stage + 1 >= NSTAGE) ? 0 : stage + 1;
    }

    const float sc = (bn < scaleCols) ? scale : 1.f;
    #pragma unroll
    for (int nt = 0; nt < 8; ++nt) {
        const int gn = bn + warp_n * 64 + nt * 8 + 2 * t;
        const float2 bz = *(const float2*)&bias[gn];
        #pragma unroll
        for (int mt = 0; mt < 2; ++mt) {
            const int gm = bm + warp_m * 32 + mt * 16 + qr;
            float2 r0, r1;
            r0.x = (acc[mt][nt][0] + bz.x) * sc;
            r0.y = (acc[mt][nt][1] + bz.y) * sc;
            r1.x = (acc[mt][nt][2] + bz.x) * sc;
            r1.y = (acc[mt][nt][3] + bz.y) * sc;
            *(float2*)&C[(size_t)gm * N + gn] = r0;
            *(float2*)&C[(size_t)(gm + 8) * N + gn] = r1;
        }
    }
}

// ---------------------------------------------------------------------------
// Neighborhood attention: fp16 k/v in smem, QK dot via HFMA2 (4 independent
// half2 accumulator chains, depth 4 -> ~1.5e-4 abs score error), fp32
// softmax + fp32 AV accumulation. Layouts unchanged from round 12.
// ---------------------------------------------------------------------------
#define TQ 8
#define WIN 14
#define KPH 56                        // halfs per k row (32 data + 24 pad)
#define K_BYTES (196 * 112)           // 21952
#define VPLANE 1576                   // halfs per v plane (197 * 8)
#define V_BYTES (4 * VPLANE * 2)      // 12608
#define ATTN_SMEM_BYTES (K_BYTES + V_BYTES + 256)   // 34816

__global__ __launch_bounds__(256) void na2d_attn(
    const float* __restrict__ qkv, const float* __restrict__ rpb,
    float* __restrict__ out)
{
    extern __shared__ float sm[];
    __half* ks_h = (__half*)sm;
    __half* vs_h = (__half*)((char*)sm + K_BYTES);
    float*  rpbs = (float*)((char*)sm + K_BYTES + V_BYTES);

    const int b    = blockIdx.z;
    const int head = blockIdx.y;
    const int tY   = blockIdx.x / 7;
    const int tX   = blockIdx.x - tY * 7;
    const int oy   = tY * TQ;
    const int ox   = tX * TQ;
    const int tid  = threadIdx.x;

    if (tid < 49) rpbs[tid] = rpb[head * 49 + tid];

    // --- load 14x14 k/v window, convert to fp16 ---
    const bool interior = (tY >= 1) && (tY <= 5) && (tX >= 1) && (tX <= 5);
    #pragma unroll 1
    for (int idx = tid; idx < 196 * 4; idx += 256) {
        const int row = idx >> 2;
        const int c   = idx & 3;
        const int wy = row / WIN, wx = row - wy * WIN;
        const int gy = oy - PADR + wy, gx = ox - PADR + wx;
        uint4 kk = make_uint4(0, 0, 0, 0);
        uint4 vv = make_uint4(0, 0, 0, 0);
        if (interior || (gy >= 0 && gy < HH && gx >= 0 && gx < WW)) {
            const float* p = qkv + (size_t)(((b * HH + gy) * WW) + gx) * QKV_N
                           + head * HD + c * 8;
            const float4 k0 = *(const float4*)(p + 256);
            const float4 k1 = *(const float4*)(p + 260);
            const float4 v0 = *(const float4*)(p + 512);
            const float4 v1 = *(const float4*)(p + 516);
            kk.x = h2u(__floats2half2_rn(k0.x, k0.y));
            kk.y = h2u(__floats2half2_rn(k0.z, k0.w));
            kk.z = h2u(__floats2half2_rn(k1.x, k1.y));
            kk.w = h2u(__floats2half2_rn(k1.z, k1.w));
            vv.x = h2u(__floats2half2_rn(v0.x, v0.y));
            vv.y = h2u(__floats2half2_rn(v0.z, v0.w));
            vv.z = h2u(__floats2half2_rn(v1.x, v1.y));
            vv.w = h2u(__floats2half2_rn(v1.z, v1.w));
        }
        *(uint4*)(ks_h + row * KPH + c * 8) = kk;        // byte: row*112 + c*16
        *(uint4*)(vs_h + c * VPLANE + row * 8) = vv;     // byte: c*3152 + row*16
    }

    // --- q into fp16 half2 registers (4 threads per query share the same q) ---
    const int qi = tid >> 2;
    const int g  = tid & 3;
    const int qy = qi >> 3, qx = qi & 7;
    const size_t qpix = (size_t)((b * HH + oy + qy) * WW) + ox + qx;
    const float4* qp = (const float4*)(qkv + qpix * QKV_N + head * HD);
    __half2 qh[16];
    #pragma unroll
    for (int cc = 0; cc < 8; ++cc) {
        const float4 qf = qp[cc];
        qh[2 * cc]     = __floats2half2_rn(qf.x, qf.y);
        qh[2 * cc + 1] = __floats2half2_rn(qf.z, qf.w);
    }

    __syncthreads();

    // --- phase 1: scores via HFMA2, 4 independent half2 chains ---
    float sv[13];
    #pragma unroll
    for (int u = 0; u < 13; ++u) {
        const int j = g + 4 * u;
        const bool act = (j < 49);
        const int jc = act ? j : 48;
        const int di = jc / 7, dj = jc - di * 7;
        const int row = (qy + di) * WIN + qx + dj;
        const uint4* kr = (const uint4*)(ks_h + row * KPH);
        const uint4 k0 = kr[0], k1 = kr[1], k2 = kr[2], k3 = kr[3];
        __half2 c0 = __hmul2(qh[0],  u2h(k0.x));
        __half2 c1 = __hmul2(qh[1],  u2h(k0.y));
        __half2 c2 = __hmul2(qh[2],  u2h(k0.z));
        __half2 c3 = __hmul2(qh[3],  u2h(k0.w));
        c0 = __hfma2(qh[4],  u2h(k1.x), c0);
        c1 = __hfma2(qh[5],  u2h(k1.y), c1);
        c2 = __hfma2(qh[6],  u2h(k1.z), c2);
        c3 = __hfma2(qh[7],  u2h(k1.w), c3);
        c0 = __hfma2(qh[8],  u2h(k2.x), c0);
        c1 = __hfma2(qh[9],  u2h(k2.y), c1);
        c2 = __hfma2(qh[10], u2h(k2.z), c2);
        c3 = __hfma2(qh[11], u2h(k2.w), c3);
        c0 = __hfma2(qh[12], u2h(k3.x), c0);
        c1 = __hfma2(qh[13], u2h(k3.y), c1);
        c2 = __hfma2(qh[14], u2h(k3.z), c2);
        c3 = __hfma2(qh[15], u2h(k3.w), c3);
        const __half2 r = __hadd2(__hadd2(c0, c1), __hadd2(c2, c3));
        const float2 f = __half22float2(r);
        sv[u] = act ? (f.x + f.y + rpbs[jc]) : -1e30f;
    }

    // --- softmax across quad (fp32); weights stay in registers ---
    float m = sv[0];
    #pragma unroll
    for (int u = 1; u < 13; ++u) m = fmaxf(m, sv[u]);
    m = fmaxf(m, __shfl_xor_sync(0xffffffffu, m, 1));
    m = fmaxf(m, __shfl_xor_sync(0xffffffffu, m, 2));
    float ssum = 0.f;
    #pragma unroll
    for (int u = 0; u < 13; ++u) {
        const float e = __expf(sv[u] - m);
        sv[u] = e;
        ssum += e;
    }
    ssum += __shfl_xor_sync(0xffffffffu, ssum, 1);
    ssum += __shfl_xor_sync(0xffffffffu, ssum, 2);
    const float inv = 1.f / ssum;
    #pragma unroll
    for (int u = 0; u < 13; ++u) sv[u] *= inv;

    // --- phase 3: AV (fp32 accumulation). thread g reads v plane g ---
    const int lanebase = (tid & 31) & ~3;
    const __half* vbase = vs_h + g * VPLANE;
    float4 a0 = make_float4(0.f, 0.f, 0.f, 0.f);
    float4 a1 = make_float4(0.f, 0.f, 0.f, 0.f);
    #pragma unroll
    for (int di = 0; di < 7; ++di) {
        const int rbase = (qy + di) * WIN + qx;
        #pragma unroll
        for (int dj = 0; dj < 7; ++dj) {
            const int j = di * 7 + dj;
            const float w = __shfl_sync(0xffffffffu, sv[j >> 2],
                                        lanebase | (j & 3));
            const uint4 vv = *(const uint4*)(vbase + (rbase + dj) * 8);
            const float2 f0 = __half22float2(u2h(vv.x));
            const float2 f1 = __half22float2(u2h(vv.y));
            const float2 f2 = __half22float2(u2h(vv.z));
            const float2 f3 = __half22float2(u2h(vv.w));
            a0.x = fmaf(w, f0.x, a0.x); a0.y = fmaf(w, f0.y, a0.y);
            a0.z = fmaf(w, f1.x, a0.z); a0.w = fmaf(w, f1.y, a0.w);
            a1.x = fmaf(w, f2.x, a1.x); a1.y = fmaf(w, f2.y, a1.y);
            a1.z = fmaf(w, f3.x, a1.z); a1.w = fmaf(w, f3.y, a1.w);
        }
    }
    // tf32-RNA-round output so the proj GEMM's in-register rounding is a no-op
    a0.x = tfr(a0.x); a0.y = tfr(a0.y); a0.z = tfr(a0.z); a0.w = tfr(a0.w);
    a1.x = tfr(a1.x); a1.y = tfr(a1.y); a1.z = tfr(a1.z); a1.w = tfr(a1.w);
    float* op = out + qpix * CC + head * HD + g * 8;
    *(float4*)op = a0;
    *(float4*)(op + 4) = a1;
}

// ---------------------------------------------------------------------------
extern "C" void kernel_launch(void* const* d_in, const int* in_sizes, int n_in,
                              void* d_out, int out_size)
{
    (void)in_sizes; (void)n_in; (void)out_size;
    const float* x      = (const float*)d_in[0];
    const float* w_qkv  = (const float*)d_in[1];
    const float* b_qkv  = (const float*)d_in[2];
    const float* rpb    = (const float*)d_in[3];
    const float* w_proj = (const float*)d_in[4];
    const float* b_proj = (const float*)d_in[5];
    float* out = (float*)d_out;

    float *qkvb = nullptr, *attnb = nullptr;
    cudaGetSymbolAddress((void**)&qkvb, g_qkv);
    cudaGetSymbolAddress((void**)&attnb, g_attn);

    cudaFuncSetAttribute(tgemm_ca, cudaFuncAttributeMaxDynamicSharedMemorySize,
                         GEMM_SMEM);
    cudaFuncSetAttribute(na2d_attn, cudaFuncAttributeMaxDynamicSharedMemorySize,
                         ATTN_SMEM_BYTES);

    const float qscale = 0.17677669529663689f; // 32^-0.5

    // 1) qkv = x @ w_qkv + b_qkv  (q columns pre-scaled)
    tgemm_ca<<<dim3(QKV_N / 128, M_TOTAL / 128), 256, GEMM_SMEM>>>(
        x, w_qkv, b_qkv, qkvb, QKV_N, 256, qscale);

    // 2) neighborhood attention ([M][C] tf32 output)
    na2d_attn<<<dim3(49, NHEAD, BATCH), 256, ATTN_SMEM_BYTES>>>(qkvb, rpb, attnb);

    // 3) out = attn @ w_proj + b_proj
    tgemm_ca<<<dim3(CC / 128, M_TOTAL / 128), 256, GEMM_SMEM>>>(
        attnb, w_proj, b_proj, out, CC, 0, 1.f);
}

// round 14
// speedup vs baseline: 1.5618x; 1.1510x over previous
#include <cuda_runtime.h>
#include <cuda_bf16.h>
#include <cuda_fp16.h>
#include <math.h>
#include <stdint.h>

// Problem constants
#define BATCH 4
#define HH 56
#define WW 56
#define CC 256
#define NHEAD 8
#define HD 32
#define KS 7
#define PADR 3
#define M_TOTAL (BATCH * HH * WW)   // 12544
#define QKV_N (3 * CC)              // 768
#define GK 256                      // K of both GEMMs

// Scratch (device globals: allocation-free rule)
__device__ float  g_qkv[M_TOTAL * QKV_N];    // [pix][768] q|k|v, q pre-scaled
__device__ __half g_attnh[M_TOTAL * CC];     // attention out [M][C], fp16
__device__ __half g_xh[M_TOTAL * CC];        // x, fp16
__device__ __half g_wqh[QKV_N * CC];         // w_qkv^T [768][256], fp16
__device__ __half g_wph[CC * CC];            // w_proj^T [256][256], fp16

__device__ __forceinline__ uint32_t smem_u32(const void* p) {
    uint32_t a;
    asm("{ .reg .u64 t; cvta.to.shared.u64 t, %1; cvt.u32.u64 %0, t; }"
        : "=r"(a) : "l"(p));
    return a;
}
__device__ __forceinline__ void cp16(uint32_t dst, const void* src) {
    asm volatile("cp.async.cg.shared.global [%0], [%1], 16;\n"
                 :: "r"(dst), "l"(src));
}
#define CP_COMMIT() asm volatile("cp.async.commit_group;\n" ::: "memory")
#define CP_WAIT2()  asm volatile("cp.async.wait_group 2;\n" ::: "memory")

__device__ __forceinline__ unsigned h2u(__half2 h) {
    return *reinterpret_cast<unsigned*>(&h);
}
__device__ __forceinline__ __half2 u2h(unsigned u) {
    return *reinterpret_cast<__half2*>(&u);
}

// ---------------------------------------------------------------------------
// Prep kernels: x -> fp16; weights -> transposed [N][K] fp16
// ---------------------------------------------------------------------------
__global__ void f32_to_f16(const float4* __restrict__ in,
                           __half* __restrict__ out, int n4)
{
    const int i = blockIdx.x * 256 + threadIdx.x;
    if (i < n4) {
        const float4 v = in[i];
        uint2 o;
        o.x = h2u(__floats2half2_rn(v.x, v.y));
        o.y = h2u(__floats2half2_rn(v.z, v.w));
        *(uint2*)(out + 4 * i) = o;
    }
}

// in [K][N] f32 -> out [N][K] f16
__global__ void transpose_h(const float* __restrict__ in,
                            __half* __restrict__ out, int K, int N)
{
    __shared__ float tile[32][33];
    const int n0 = blockIdx.x * 32, k0 = blockIdx.y * 32;
    for (int i = threadIdx.y; i < 32; i += 8)
        tile[i][threadIdx.x] = in[(size_t)(k0 + i) * N + n0 + threadIdx.x];
    __syncthreads();
    for (int i = threadIdx.y; i < 32; i += 8)
        out[(size_t)(n0 + i) * K + k0 + threadIdx.x] =
            __float2half_rn(tile[threadIdx.x][i]);
}

// ---------------------------------------------------------------------------
// cp.async 4-stage FP16 GEMM: C[M][N] = A @ Bt^T + bias (fp32 accumulate).
// A [M][K=256] fp16 row-major, Bt [N][K=256] fp16 row-major.
// Block tile 128x128x32, 256 thr = 8 warps (4Mx2N), warp tile 32x64,
// mma.m16n8k16.f32.f16.f16.f32. Smem [m][k]/[n][k] pitch 40 halfs ->
// fragment bank = 20*qr+t mod 32, conflict-free. 4 stages = 80KB,
// 2 blocks/SM, 3-tile lookahead.
// ---------------------------------------------------------------------------
#define NSTAGE 4
#define PITCH_H 40                     // halfs per row (32 + 8 pad)
#define ASTG_B (128 * PITCH_H * 2)     // 10240
#define BSTG_B (128 * PITCH_H * 2)     // 10240
#define STG_B  (ASTG_B + BSTG_B)       // 20480
#define GEMM_SMEM (NSTAGE * STG_B)     // 81920

__device__ __forceinline__ void mma_f16(float4& d,
    unsigned a0, unsigned a1, unsigned a2, unsigned a3,
    unsigned b0, unsigned b1)
{
    asm volatile(
        "mma.sync.aligned.m16n8k16.row.col.f32.f16.f16.f32 "
        "{%0,%1,%2,%3},{%4,%5,%6,%7},{%8,%9},{%0,%1,%2,%3};\n"
        : "+f"(d.x), "+f"(d.y), "+f"(d.z), "+f"(d.w)
        : "r"(a0), "r"(a1), "r"(a2), "r"(a3), "r"(b0), "r"(b1));
}

__global__ __launch_bounds__(256, 2) void tgemm_h(
    const __half* __restrict__ A, const __half* __restrict__ Bt,
    const float* __restrict__ bias, float* __restrict__ C,
    int N, int scaleCols, float scale)
{
    extern __shared__ float sm[];
    const uint32_t sb = smem_u32(sm);
    __half* smh = (__half*)sm;
    const int tid  = threadIdx.x;
    const int wid  = tid >> 5;
    const int lane = tid & 31;
    const int warp_m = wid & 3;        // 4 warps along M (32 rows)
    const int warp_n = wid >> 2;       // 2 warps along N (64 cols)
    const int t  = lane & 3;
    const int qr = lane >> 2;
    const int bm = blockIdx.y << 7;
    const int bn = blockIdx.x << 7;

    // load mapping: row lr = tid>>2 (0..63) and lr+64; chunk lc = tid&3 (8 halfs)
    const int lr = tid >> 2;
    const int lc = tid & 3;
    const __half* Asrc = A + (size_t)(bm + lr) * GK + lc * 8;
    const __half* Bsrc = Bt + (size_t)(bn + lr) * GK + lc * 8;
    const uint32_t aOff = (uint32_t)(lr * PITCH_H + lc * 8) * 2u;
    const uint32_t bOff = (uint32_t)ASTG_B + aOff;
    const uint32_t rowStep = 64u * PITCH_H * 2u;   // +64 rows in bytes

    float acc[2][8][4];
    #pragma unroll
    for (int mt = 0; mt < 2; ++mt)
        #pragma unroll
        for (int nt = 0; nt < 8; ++nt)
            #pragma unroll
            for (int i = 0; i < 4; ++i) acc[mt][nt][i] = 0.f;

    // prologue: stages 0..2 <- k-tiles 0..2
    #pragma unroll
    for (int s = 0; s < NSTAGE - 1; ++s) {
        const uint32_t sd = sb + s * STG_B;
        cp16(sd + aOff, Asrc + s * 32);
        cp16(sd + aOff + rowStep, Asrc + (size_t)64 * GK + s * 32);
        cp16(sd + bOff, Bsrc + s * 32);
        cp16(sd + bOff + rowStep, Bsrc + (size_t)64 * GK + s * 32);
        CP_COMMIT();
    }

    #pragma unroll 1
    for (int kt = 0; kt < 8; ++kt) {
        CP_WAIT2();          // <=2 pending groups -> tile kt resident
        __syncthreads();

        if (kt + 3 < 8) {
            const uint32_t sd = sb + ((kt + 3) & 3) * STG_B;
            cp16(sd + aOff, Asrc + (kt + 3) * 32);
            cp16(sd + aOff + rowStep, Asrc + (size_t)64 * GK + (kt + 3) * 32);
            cp16(sd + bOff, Bsrc + (kt + 3) * 32);
            cp16(sd + bOff + rowStep, Bsrc + (size_t)64 * GK + (kt + 3) * 32);
        }
        CP_COMMIT();         // always commit (keeps wait_group arithmetic exact)

        const __half* as = smh + (kt & 3) * (STG_B / 2)
                         + (warp_m * 32) * PITCH_H;
        const __half* bs = smh + (kt & 3) * (STG_B / 2) + (ASTG_B / 2)
                         + (warp_n * 64) * PITCH_H;
        #pragma unroll
        for (int ks = 0; ks < 2; ++ks) {
            const __half* ap = as + ks * 16 + 2 * t;
            const __half* bp = bs + ks * 16 + 2 * t;
            unsigned a0[2], a1[2], a2[2], a3[2];
            #pragma unroll
            for (int mt = 0; mt < 2; ++mt) {
                const __half* r0 = ap + (mt * 16 + qr) * PITCH_H;
                const __half* r1 = ap + (mt * 16 + qr + 8) * PITCH_H;
                a0[mt] = *(const unsigned*)r0;
                a1[mt] = *(const unsigned*)r1;
                a2[mt] = *(const unsigned*)(r0 + 8);
                a3[mt] = *(const unsigned*)(r1 + 8);
            }
            unsigned b0[8], b1[8];
            #pragma unroll
            for (int nt = 0; nt < 8; ++nt) {
                const __half* rn = bp + (nt * 8 + qr) * PITCH_H;
                b0[nt] = *(const unsigned*)rn;
                b1[nt] = *(const unsigned*)(rn + 8);
            }
            #pragma unroll
            for (int mt = 0; mt < 2; ++mt)
                #pragma unroll
                for (int nt = 0; nt < 8; ++nt)
                    mma_f16(*(float4*)acc[mt][nt],
                            a0[mt], a1[mt], a2[mt], a3[mt],
                            b0[nt], b1[nt]);
        }
    }

    const float sc = (bn < scaleCols) ? scale : 1.f;
    #pragma unroll
    for (int nt = 0; nt < 8; ++nt) {
        const int gn = bn + warp_n * 64 + nt * 8 + 2 * t;
        const float2 bz = *(const float2*)&bias[gn];
        #pragma unroll
        for (int mt = 0; mt < 2; ++mt) {
            const int gm = bm + warp_m * 32 + mt * 16 + qr;
            float2 r0, r1;
            r0.x = (acc[mt][nt][0] + bz.x) * sc;
            r0.y = (acc[mt][nt][1] + bz.y) * sc;
            r1.x = (acc[mt][nt][2] + bz.x) * sc;
            r1.y = (acc[mt][nt][3] + bz.y) * sc;
            *(float2*)&C[(size_t)gm * N + gn] = r0;
            *(float2*)&C[(size_t)(gm + 8) * N + gn] = r1;
        }
    }
}

// ---------------------------------------------------------------------------
// Neighborhood attention (round-13 body): fp16 k/v smem, HFMA2 QK, fp32
// softmax + fp32 AV. Output now written as fp16 (proj GEMM A operand).
// ---------------------------------------------------------------------------
#define TQ 8
#define WIN 14
#define KPH 56                        // halfs per k row (32 data + 24 pad)
#define K_BYTES (196 * 112)           // 21952
#define VPLANE 1576                   // halfs per v plane (197 * 8)
#define V_BYTES (4 * VPLANE * 2)      // 12608
#define ATTN_SMEM_BYTES (K_BYTES + V_BYTES + 256)   // 34816

__global__ __launch_bounds__(256) void na2d_attn(
    const float* __restrict__ qkv, const float* __restrict__ rpb,
    __half* __restrict__ out)
{
    extern __shared__ float sm[];
    __half* ks_h = (__half*)sm;
    __half* vs_h = (__half*)((char*)sm + K_BYTES);
    float*  rpbs = (float*)((char*)sm + K_BYTES + V_BYTES);

    const int b    = blockIdx.z;
    const int head = blockIdx.y;
    const int tY   = blockIdx.x / 7;
    const int tX   = blockIdx.x - tY * 7;
    const int oy   = tY * TQ;
    const int ox   = tX * TQ;
    const int tid  = threadIdx.x;

    if (tid < 49) rpbs[tid] = rpb[head * 49 + tid];

    const bool interior = (tY >= 1) && (tY <= 5) && (tX >= 1) && (tX <= 5);
    #pragma unroll 1
    for (int idx = tid; idx < 196 * 4; idx += 256) {
        const int row = idx >> 2;
        const int c   = idx & 3;
        const int wy = row / WIN, wx = row - wy * WIN;
        const int gy = oy - PADR + wy, gx = ox - PADR + wx;
        uint4 kk = make_uint4(0, 0, 0, 0);
        uint4 vv = make_uint4(0, 0, 0, 0);
        if (interior || (gy >= 0 && gy < HH && gx >= 0 && gx < WW)) {
            const float* p = qkv + (size_t)(((b * HH + gy) * WW) + gx) * QKV_N
                           + head * HD + c * 8;
            const float4 k0 = *(const float4*)(p + 256);
            const float4 k1 = *(const float4*)(p + 260);
            const float4 v0 = *(const float4*)(p + 512);
            const float4 v1 = *(const float4*)(p + 516);
            kk.x = h2u(__floats2half2_rn(k0.x, k0.y));
            kk.y = h2u(__floats2half2_rn(k0.z, k0.w));
            kk.z = h2u(__floats2half2_rn(k1.x, k1.y));
            kk.w = h2u(__floats2half2_rn(k1.z, k1.w));
            vv.x = h2u(__floats2half2_rn(v0.x, v0.y));
            vv.y = h2u(__floats2half2_rn(v0.z, v0.w));
            vv.z = h2u(__floats2half2_rn(v1.x, v1.y));
            vv.w = h2u(__floats2half2_rn(v1.z, v1.w));
        }
        *(uint4*)(ks_h + row * KPH + c * 8) = kk;
        *(uint4*)(vs_h + c * VPLANE + row * 8) = vv;
    }

    const int qi = tid >> 2;
    const int g  = tid & 3;
    const int qy = qi >> 3, qx = qi & 7;
    const size_t qpix = (size_t)((b * HH + oy + qy) * WW) + ox + qx;
    const float4* qp = (const float4*)(qkv + qpix * QKV_N + head * HD);
    __half2 qh[16];
    #pragma unroll
    for (int cc = 0; cc < 8; ++cc) {
        const float4 qf = qp[cc];
        qh[2 * cc]     = __floats2half2_rn(qf.x, qf.y);
        qh[2 * cc + 1] = __floats2half2_rn(qf.z, qf.w);
    }

    __syncthreads();

    float sv[13];
    #pragma unroll
    for (int u = 0; u < 13; ++u) {
        const int j = g + 4 * u;
        const bool act = (j < 49);
        const int jc = act ? j : 48;
        const int di = jc / 7, dj = jc - di * 7;
        const int row = (qy + di) * WIN + qx + dj;
        const uint4* kr = (const uint4*)(ks_h + row * KPH);
        const uint4 k0 = kr[0], k1 = kr[1], k2 = kr[2], k3 = kr[3];
        __half2 c0 = __hmul2(qh[0],  u2h(k0.x));
        __half2 c1 = __hmul2(qh[1],  u2h(k0.y));
        __half2 c2 = __hmul2(qh[2],  u2h(k0.z));
        __half2 c3 = __hmul2(qh[3],  u2h(k0.w));
        c0 = __hfma2(qh[4],  u2h(k1.x), c0);
        c1 = __hfma2(qh[5],  u2h(k1.y), c1);
        c2 = __hfma2(qh[6],  u2h(k1.z), c2);
        c3 = __hfma2(qh[7],  u2h(k1.w), c3);
        c0 = __hfma2(qh[8],  u2h(k2.x), c0);
        c1 = __hfma2(qh[9],  u2h(k2.y), c1);
        c2 = __hfma2(qh[10], u2h(k2.z), c2);
        c3 = __hfma2(qh[11], u2h(k2.w), c3);
        c0 = __hfma2(qh[12], u2h(k3.x), c0);
        c1 = __hfma2(qh[13], u2h(k3.y), c1);
        c2 = __hfma2(qh[14], u2h(k3.z), c2);
        c3 = __hfma2(qh[15], u2h(k3.w), c3);
        const __half2 r = __hadd2(__hadd2(c0, c1), __hadd2(c2, c3));
        const float2 f = __half22float2(r);
        sv[u] = act ? (f.x + f.y + rpbs[jc]) : -1e30f;
    }

    float m = sv[0];
    #pragma unroll
    for (int u = 1; u < 13; ++u) m = fmaxf(m, sv[u]);
    m = fmaxf(m, __shfl_xor_sync(0xffffffffu, m, 1));
    m = fmaxf(m, __shfl_xor_sync(0xffffffffu, m, 2));
    float ssum = 0.f;
    #pragma unroll
    for (int u = 0; u < 13; ++u) {
        const float e = __expf(sv[u] - m);
        sv[u] = e;
        ssum += e;
    }
    ssum += __shfl_xor_sync(0xffffffffu, ssum, 1);
    ssum += __shfl_xor_sync(0xffffffffu, ssum, 2);
    const float inv = 1.f / ssum;
    #pragma unroll
    for (int u = 0; u < 13; ++u) sv[u] *= inv;

    const int lanebase = (tid & 31) & ~3;
    const __half* vbase = vs_h + g * VPLANE;
    float4 a0 = make_float4(0.f, 0.f, 0.f, 0.f);
    float4 a1 = make_float4(0.f, 0.f, 0.f, 0.f);
    #pragma unroll
    for (int di = 0; di < 7; ++di) {
        const int rbase = (qy + di) * WIN + qx;
        #pragma unroll
        for (int dj = 0; dj < 7; ++dj) {
            const int j = di * 7 + dj;
            const float w = __shfl_sync(0xffffffffu, sv[j >> 2],
                                        lanebase | (j & 3));
            const uint4 vv = *(const uint4*)(vbase + (rbase + dj) * 8);
            const float2 f0 = __half22float2(u2h(vv.x));
            const float2 f1 = __half22float2(u2h(vv.y));
            const float2 f2 = __half22float2(u2h(vv.z));
            const float2 f3 = __half22float2(u2h(vv.w));
            a0.x = fmaf(w, f0.x, a0.x); a0.y = fmaf(w, f0.y, a0.y);
            a0.z = fmaf(w, f1.x, a0.z); a0.w = fmaf(w, f1.y, a0.w);
            a1.x = fmaf(w, f2.x, a1.x); a1.y = fmaf(w, f2.y, a1.y);
            a1.z = fmaf(w, f3.x, a1.z); a1.w = fmaf(w, f3.y, a1.w);
        }
    }
    // fp16 output (replaces the previous tf32 rounding; same error quantum)
    uint4 o;
    o.x = h2u(__floats2half2_rn(a0.x, a0.y));
    o.y = h2u(__floats2half2_rn(a0.z, a0.w));
    o.z = h2u(__floats2half2_rn(a1.x, a1.y));
    o.w = h2u(__floats2half2_rn(a1.z, a1.w));
    *(uint4*)(out + qpix * CC + head * HD + g * 8) = o;
}

// ---------------------------------------------------------------------------
extern "C" void kernel_launch(void* const* d_in, const int* in_sizes, int n_in,
                              void* d_out, int out_size)
{
    (void)in_sizes; (void)n_in; (void)out_size;
    const float* x      = (const float*)d_in[0];
    const float* w_qkv  = (const float*)d_in[1];
    const float* b_qkv  = (const float*)d_in[2];
    const float* rpb    = (const float*)d_in[3];
    const float* w_proj = (const float*)d_in[4];
    const float* b_proj = (const float*)d_in[5];
    float* out = (float*)d_out;

    float* qkvb = nullptr;
    __half *attnh = nullptr, *xh = nullptr, *wqh = nullptr, *wph = nullptr;
    cudaGetSymbolAddress((void**)&qkvb, g_qkv);
    cudaGetSymbolAddress((void**)&attnh, g_attnh);
    cudaGetSymbolAddress((void**)&xh, g_xh);
    cudaGetSymbolAddress((void**)&wqh, g_wqh);
    cudaGetSymbolAddress((void**)&wph, g_wph);

    cudaFuncSetAttribute(tgemm_h, cudaFuncAttributeMaxDynamicSharedMemorySize,
                         GEMM_SMEM);
    cudaFuncSetAttribute(na2d_attn, cudaFuncAttributeMaxDynamicSharedMemorySize,
                         ATTN_SMEM_BYTES);

    const float qscale = 0.17677669529663689f; // 32^-0.5

    // 0) prep: x -> fp16; weights -> transposed [N][K] fp16
    {
        const int nx = M_TOTAL * CC / 4;
        f32_to_f16<<<(nx + 255) / 256, 256>>>((const float4*)x, xh, nx);
        transpose_h<<<dim3(QKV_N / 32, CC / 32), dim3(32, 8)>>>(w_qkv, wqh, CC, QKV_N);
        transpose_h<<<dim3(CC / 32, CC / 32), dim3(32, 8)>>>(w_proj, wph, CC, CC);
    }

    // 1) qkv = x @ w_qkv + b_qkv  (q columns pre-scaled)
    tgemm_h<<<dim3(QKV_N / 128, M_TOTAL / 128), 256, GEMM_SMEM>>>(
        xh, wqh, b_qkv, qkvb, QKV_N, 256, qscale);

    // 2) neighborhood attention (fp16 output for proj GEMM)
    na2d_attn<<<dim3(49, NHEAD, BATCH), 256, ATTN_SMEM_BYTES>>>(qkvb, rpb, attnh);

    // 3) out = attn @ w_proj + b_proj
    tgemm_h<<<dim3(CC / 128, M_TOTAL / 128), 256, GEMM_SMEM>>>(
        attnh, wph, b_proj, out, CC, 0, 1.f);
}